// round 13
// baseline (speedup 1.0000x reference)
#include <cuda_runtime.h>
#include <math.h>
#include <math_constants.h>

#define NN 50000
#define EE 640000
#define DIN 256
#define DD 128
#define HH 8
#define NCC 47
#define LL 3

// ---------------- scratch (static device allocations; no runtime alloc) ----
__device__ float g_h[NN * DD];
__device__ float g_agg[NN * DD];
__device__ float g_t[NN * 512];       // qkv [N,384] per layer; also ff1 [N,512]
__device__ float g_t2[NN * 512];      // ff2 [N,512]
__device__ float g_wqkv[LL * DD * 384];
__device__ int   g_deg[NN];
__device__ int   g_off[NN + 1];
__device__ int   g_cur[NN];
__device__ int   g_csr[EE];

// ---------------- CSR build ------------------------------------------------
__global__ void zero_deg_kernel() {
    int i = blockIdx.x * blockDim.x + threadIdx.x;
    if (i < NN) g_deg[i] = 0;
}

__global__ void count_deg_kernel(const int* __restrict__ dst) {
    int e = blockIdx.x * blockDim.x + threadIdx.x;
    if (e < EE) atomicAdd(&g_deg[dst[e]], 1);
}

__global__ void scan_kernel() {
    __shared__ int wsum[32];
    __shared__ int carry_s;
    int t = threadIdx.x, lane = t & 31, wid = t >> 5;
    if (t == 0) carry_s = 0;
    __syncthreads();
    for (int base = 0; base < NN; base += 1024) {
        int i = base + t;
        int val = (i < NN) ? g_deg[i] : 0;
        int incl = val;
        #pragma unroll
        for (int o = 1; o < 32; o <<= 1) {
            int x = __shfl_up_sync(0xFFFFFFFFu, incl, o);
            if (lane >= o) incl += x;
        }
        if (lane == 31) wsum[wid] = incl;
        __syncthreads();
        if (wid == 0) {
            int wv = wsum[lane];
            int wincl = wv;
            #pragma unroll
            for (int o = 1; o < 32; o <<= 1) {
                int x = __shfl_up_sync(0xFFFFFFFFu, wincl, o);
                if (lane >= o) wincl += x;
            }
            wsum[lane] = wincl - wv;
        }
        __syncthreads();
        int carry = carry_s;
        int excl = carry + wsum[wid] + incl - val;
        if (i < NN) { g_off[i] = excl; g_cur[i] = excl; }
        __syncthreads();
        if (t == 1023) carry_s = carry + wsum[31] + incl;
        __syncthreads();
    }
    if (threadIdx.x == 0) g_off[NN] = carry_s;
}

__global__ void scatter_kernel(const int* __restrict__ src, const int* __restrict__ dst) {
    int e = blockIdx.x * blockDim.x + threadIdx.x;
    if (e < EE) {
        int d = dst[e];
        int pos = atomicAdd(&g_cur[d], 1);
        g_csr[pos] = src[e];
    }
}

// ---------------- pack Wq|Wk|Wv -> [L][128][384] ---------------------------
__global__ void pack_qkv_kernel(const float* __restrict__ Wq,
                                const float* __restrict__ Wk,
                                const float* __restrict__ Wv) {
    int i = blockIdx.x * blockDim.x + threadIdx.x;
    if (i < LL * DD * DD) {
        int l = i / (DD * DD);
        int r = (i / DD) % DD;
        int c = i % DD;
        size_t o = ((size_t)l * DD + r) * 384;
        g_wqkv[o + c]       = Wq[i];
        g_wqkv[o + 128 + c] = Wk[i];
        g_wqkv[o + 256 + c] = Wv[i];
    }
}

__device__ __forceinline__ unsigned f2tf(float f) {
    unsigned u;
    asm("cvt.rna.tf32.f32 %0, %1;" : "=r"(u) : "f"(f));
    return u;
}

#define MMA_TF32(d, a0, a1, a2, a3, b0, b1)                              \
    asm volatile(                                                        \
        "mma.sync.aligned.m16n8k8.row.col.f32.tf32.tf32.f32 "            \
        "{%0,%1,%2,%3}, {%4,%5,%6,%7}, {%8,%9}, {%0,%1,%2,%3};"          \
        : "+f"(d[0]), "+f"(d[1]), "+f"(d[2]), "+f"(d[3])                 \
        : "r"(a0), "r"(a1), "r"(a2), "r"(a3), "r"(b0), "r"(b1))

// ============ GEMM-A: BM=128,BN=128, 32x64 warp tile (proven; LN fusion) ===
#define GEMM_SMEM_BYTES (2 * 2 * 16 * 136 * 4)

template <int BIAS, int RELU, int LN>
__global__ void __launch_bounds__(256, 2)
tf32gemm_kernel(const float* __restrict__ A, const float* __restrict__ B,
                const float* __restrict__ bias, float* __restrict__ C,
                int M, int N, int K,
                const float* __restrict__ resid,
                const float* __restrict__ lngam,
                const float* __restrict__ lnbet) {
    extern __shared__ unsigned sm[];
    unsigned (*As)[16][136] = (unsigned (*)[16][136])sm;
    unsigned (*Bs)[16][136] = (unsigned (*)[16][136])(sm + 2 * 16 * 136);

    int tid = threadIdx.x, lane = tid & 31, wid = tid >> 5;
    int row0 = blockIdx.y * 128, col0 = blockIdx.x * 128;
    int wm = (wid & 3) * 32, wn = (wid >> 2) * 64;
    int g = lane >> 2, c = lane & 3;

    int aRow = tid >> 1, aSeg = tid & 1;
    int bRow = tid >> 5;
    int gr = row0 + aRow;
    int gc = col0 + lane * 4;

    const bool nVec = ((N & 127) == 0);
    const bool nEven = ((N & 1) == 0);

    float acc[2][8][4];
    #pragma unroll
    for (int i = 0; i < 2; i++)
        #pragma unroll
        for (int j = 0; j < 8; j++)
            #pragma unroll
            for (int r = 0; r < 4; r++) acc[i][j][r] = 0.f;

    float4 pa0, pa1, pb0, pb1;

    auto fetch = [&](int k0) {
        pa0 = make_float4(0.f, 0.f, 0.f, 0.f); pa1 = pa0;
        if (gr < M) {
            const float* ap = A + (size_t)gr * K + k0 + aSeg * 8;
            pa0 = ((const float4*)ap)[0];
            pa1 = ((const float4*)ap)[1];
        }
        const float* bp0 = B + (size_t)(k0 + bRow) * N + gc;
        const float* bp1 = B + (size_t)(k0 + bRow + 8) * N + gc;
        if (nVec) {
            pb0 = *(const float4*)bp0;
            pb1 = *(const float4*)bp1;
        } else {
            pb0.x = (gc + 0 < N) ? bp0[0] : 0.f;
            pb0.y = (gc + 1 < N) ? bp0[1] : 0.f;
            pb0.z = (gc + 2 < N) ? bp0[2] : 0.f;
            pb0.w = (gc + 3 < N) ? bp0[3] : 0.f;
            pb1.x = (gc + 0 < N) ? bp1[0] : 0.f;
            pb1.y = (gc + 1 < N) ? bp1[1] : 0.f;
            pb1.z = (gc + 2 < N) ? bp1[2] : 0.f;
            pb1.w = (gc + 3 < N) ? bp1[3] : 0.f;
        }
    };
    auto stage = [&](int s) {
        int kb = aSeg * 8;
        As[s][kb + 0][aRow] = f2tf(pa0.x);
        As[s][kb + 1][aRow] = f2tf(pa0.y);
        As[s][kb + 2][aRow] = f2tf(pa0.z);
        As[s][kb + 3][aRow] = f2tf(pa0.w);
        As[s][kb + 4][aRow] = f2tf(pa1.x);
        As[s][kb + 5][aRow] = f2tf(pa1.y);
        As[s][kb + 6][aRow] = f2tf(pa1.z);
        As[s][kb + 7][aRow] = f2tf(pa1.w);
        Bs[s][bRow][lane * 4 + 0] = f2tf(pb0.x);
        Bs[s][bRow][lane * 4 + 1] = f2tf(pb0.y);
        Bs[s][bRow][lane * 4 + 2] = f2tf(pb0.z);
        Bs[s][bRow][lane * 4 + 3] = f2tf(pb0.w);
        Bs[s][bRow + 8][lane * 4 + 0] = f2tf(pb1.x);
        Bs[s][bRow + 8][lane * 4 + 1] = f2tf(pb1.y);
        Bs[s][bRow + 8][lane * 4 + 2] = f2tf(pb1.z);
        Bs[s][bRow + 8][lane * 4 + 3] = f2tf(pb1.w);
    };

    fetch(0);
    stage(0);
    __syncthreads();

    int s = 0;
    for (int k0 = 0; k0 < K; k0 += 16) {
        bool hasNext = (k0 + 16) < K;
        if (hasNext) fetch(k0 + 16);

        #pragma unroll
        for (int ks = 0; ks < 2; ks++) {
            int kb = ks * 8;
            unsigned a[2][4];
            #pragma unroll
            for (int i = 0; i < 2; i++) {
                int m = wm + 16 * i + g;
                a[i][0] = As[s][kb + c][m];
                a[i][1] = As[s][kb + c][m + 8];
                a[i][2] = As[s][kb + c + 4][m];
                a[i][3] = As[s][kb + c + 4][m + 8];
            }
            #pragma unroll
            for (int j = 0; j < 8; j++) {
                unsigned b0 = Bs[s][kb + c][wn + 8 * j + g];
                unsigned b1 = Bs[s][kb + c + 4][wn + 8 * j + g];
                #pragma unroll
                for (int i = 0; i < 2; i++) {
                    MMA_TF32(acc[i][j], a[i][0], a[i][1], a[i][2], a[i][3], b0, b1);
                }
            }
        }

        if (hasNext) {
            stage(s ^ 1);
            __syncthreads();
            s ^= 1;
        }
    }

    if (LN) {
        // ---- fused LayerNorm epilogue (N==128, one block per 128 rows) ----
        __syncthreads();
        float* rsum = (float*)sm;
        float* rsq  = (float*)sm + 256;
        int half = wn >> 6;
        #pragma unroll
        for (int i = 0; i < 2; i++) {
            #pragma unroll
            for (int hh = 0; hh < 2; hh++) {
                int lr = wm + 16 * i + 8 * hh + g;
                int rr = row0 + lr;
                float s16 = 0.f, q16 = 0.f;
                #pragma unroll
                for (int j = 0; j < 8; j++) {
                    int cc = wn + 8 * j + 2 * c;
                    float v0 = acc[i][j][2 * hh + 0];
                    float v1 = acc[i][j][2 * hh + 1];
                    if (BIAS) { v0 += bias[cc]; v1 += bias[cc + 1]; }
                    if (RELU) { v0 = fmaxf(v0, 0.f); v1 = fmaxf(v1, 0.f); }
                    if (resid != nullptr && rr < M) {
                        float2 rv = *(const float2*)(resid + (size_t)rr * 128 + cc);
                        v0 += rv.x; v1 += rv.y;
                    }
                    acc[i][j][2 * hh + 0] = v0;
                    acc[i][j][2 * hh + 1] = v1;
                    s16 += v0 + v1;
                    q16 += v0 * v0 + v1 * v1;
                }
                s16 += __shfl_xor_sync(0xFFFFFFFFu, s16, 1);
                s16 += __shfl_xor_sync(0xFFFFFFFFu, s16, 2);
                q16 += __shfl_xor_sync(0xFFFFFFFFu, q16, 1);
                q16 += __shfl_xor_sync(0xFFFFFFFFu, q16, 2);
                if (c == 0) {
                    rsum[half * 128 + lr] = s16;
                    rsq [half * 128 + lr] = q16;
                }
            }
        }
        __syncthreads();
        #pragma unroll
        for (int i = 0; i < 2; i++) {
            #pragma unroll
            for (int hh = 0; hh < 2; hh++) {
                int lr = wm + 16 * i + 8 * hh + g;
                int rr = row0 + lr;
                if (rr >= M) continue;
                float tot = rsum[lr] + rsum[128 + lr];
                float tq  = rsq[lr]  + rsq[128 + lr];
                float mu  = tot * (1.f / 128.f);
                float var = tq * (1.f / 128.f) - mu * mu;
                float rstd = rsqrtf(var + 1e-5f);
                #pragma unroll
                for (int j = 0; j < 8; j++) {
                    int cc = wn + 8 * j + 2 * c;
                    float2 gg = *(const float2*)(lngam + cc);
                    float2 bb = *(const float2*)(lnbet + cc);
                    float y0 = (acc[i][j][2 * hh + 0] - mu) * rstd * gg.x + bb.x;
                    float y1 = (acc[i][j][2 * hh + 1] - mu) * rstd * gg.y + bb.y;
                    *(float2*)(C + (size_t)rr * 128 + cc) = make_float2(y0, y1);
                }
            }
        }
        return;
    }

    // ---- plain epilogue ----
    #pragma unroll
    for (int i = 0; i < 2; i++) {
        int r = row0 + wm + 16 * i + g;
        #pragma unroll
        for (int j = 0; j < 8; j++) {
            int cc = col0 + wn + 8 * j + 2 * c;
            #pragma unroll
            for (int hh = 0; hh < 2; hh++) {
                int rr = r + hh * 8;
                if (rr < M) {
                    float v0 = acc[i][j][hh * 2 + 0];
                    float v1 = acc[i][j][hh * 2 + 1];
                    float* cp = C + (size_t)rr * N + cc;
                    if (nEven) {
                        if (cc + 1 < N) {
                            if (BIAS) { v0 += bias[cc]; v1 += bias[cc + 1]; }
                            if (RELU) { v0 = fmaxf(v0, 0.f); v1 = fmaxf(v1, 0.f); }
                            *(float2*)cp = make_float2(v0, v1);
                        } else if (cc < N) {
                            if (BIAS) v0 += bias[cc];
                            if (RELU) v0 = fmaxf(v0, 0.f);
                            cp[0] = v0;
                        }
                    } else {
                        if (cc < N) {
                            if (BIAS) v0 += bias[cc];
                            if (RELU) v0 = fmaxf(v0, 0.f);
                            cp[0] = v0;
                        }
                        if (cc + 1 < N) {
                            if (BIAS) v1 += bias[cc + 1];
                            if (RELU) v1 = fmaxf(v1, 0.f);
                            cp[1] = v1;
                        }
                    }
                }
            }
        }
    }
}

// ============ GEMM-B: BM=128,BN=256, 64x64 warp tile (issue-dense) =========
// 8 warps in 2(M)x4(N); acc[4][8][4]=128 regs; 1 block/SM. Requires N>=256,
// N%8==0, vector loads valid for cols [col0,col0+256) with col0=min(bx*256,N-256).
#define G2_SMEM_U32 (2 * 16 * 136 + 2 * 16 * 264)
#define G2_SMEM_BYTES (G2_SMEM_U32 * 4)

template <int BIAS, int RELU>
__global__ void __launch_bounds__(256, 1)
tf32gemm256_kernel(const float* __restrict__ A, const float* __restrict__ B,
                   const float* __restrict__ bias, float* __restrict__ C,
                   int M, int N, int K) {
    extern __shared__ unsigned sm[];
    unsigned (*As)[16][136] = (unsigned (*)[16][136])sm;            // [2]
    unsigned (*Bs)[16][264] = (unsigned (*)[16][264])(sm + 2 * 16 * 136);

    int tid = threadIdx.x, lane = tid & 31, wid = tid >> 5;
    int row0 = blockIdx.y * 128;
    int col0 = min((int)blockIdx.x * 256, N - 256);
    int wm = (wid & 1) * 64, wn = (wid >> 1) * 64;
    int g = lane >> 2, c = lane & 3;

    int aRow = tid >> 1, aSeg = tid & 1;
    int bRow = tid >> 5;
    int gr = row0 + aRow;
    int gc = col0 + lane * 8;

    float acc[4][8][4];
    #pragma unroll
    for (int t = 0; t < 4; t++)
        #pragma unroll
        for (int j = 0; j < 8; j++)
            #pragma unroll
            for (int r = 0; r < 4; r++) acc[t][j][r] = 0.f;

    float4 pa0, pa1, pb[4];

    auto fetch = [&](int k0) {
        pa0 = make_float4(0.f, 0.f, 0.f, 0.f); pa1 = pa0;
        if (gr < M) {
            const float* ap = A + (size_t)gr * K + k0 + aSeg * 8;
            pa0 = ((const float4*)ap)[0];
            pa1 = ((const float4*)ap)[1];
        }
        const float* bp0 = B + (size_t)(k0 + bRow) * N + gc;
        const float* bp1 = B + (size_t)(k0 + bRow + 8) * N + gc;
        pb[0] = ((const float4*)bp0)[0];
        pb[1] = ((const float4*)bp0)[1];
        pb[2] = ((const float4*)bp1)[0];
        pb[3] = ((const float4*)bp1)[1];
    };
    auto stage = [&](int s) {
        int kb = aSeg * 8;
        As[s][kb + 0][aRow] = f2tf(pa0.x);
        As[s][kb + 1][aRow] = f2tf(pa0.y);
        As[s][kb + 2][aRow] = f2tf(pa0.z);
        As[s][kb + 3][aRow] = f2tf(pa0.w);
        As[s][kb + 4][aRow] = f2tf(pa1.x);
        As[s][kb + 5][aRow] = f2tf(pa1.y);
        As[s][kb + 6][aRow] = f2tf(pa1.z);
        As[s][kb + 7][aRow] = f2tf(pa1.w);
        #pragma unroll
        for (int r = 0; r < 2; r++) {
            #pragma unroll
            for (int q = 0; q < 2; q++) {
                float4 v = pb[r * 2 + q];
                uint4 u = make_uint4(f2tf(v.x), f2tf(v.y), f2tf(v.z), f2tf(v.w));
                *(uint4*)&Bs[s][bRow + r * 8][lane * 8 + q * 4] = u;
            }
        }
    };

    fetch(0);
    stage(0);
    __syncthreads();

    int s = 0;
    for (int k0 = 0; k0 < K; k0 += 16) {
        bool hasNext = (k0 + 16) < K;
        if (hasNext) fetch(k0 + 16);

        #pragma unroll
        for (int ks = 0; ks < 2; ks++) {
            int kb = ks * 8;
            unsigned a[4][4];
            #pragma unroll
            for (int t = 0; t < 4; t++) {
                int m = wm + 16 * t + g;
                a[t][0] = As[s][kb + c][m];
                a[t][1] = As[s][kb + c][m + 8];
                a[t][2] = As[s][kb + c + 4][m];
                a[t][3] = As[s][kb + c + 4][m + 8];
            }
            #pragma unroll
            for (int j = 0; j < 8; j++) {
                unsigned b0 = Bs[s][kb + c][wn + 8 * j + g];
                unsigned b1 = Bs[s][kb + c + 4][wn + 8 * j + g];
                #pragma unroll
                for (int t = 0; t < 4; t++) {
                    MMA_TF32(acc[t][j], a[t][0], a[t][1], a[t][2], a[t][3], b0, b1);
                }
            }
        }

        if (hasNext) {
            stage(s ^ 1);
            __syncthreads();
            s ^= 1;
        }
    }

    // epilogue (always even N, vector float2 stores valid)
    #pragma unroll
    for (int t = 0; t < 4; t++) {
        #pragma unroll
        for (int j = 0; j < 8; j++) {
            int cc = col0 + wn + 8 * j + 2 * c;
            #pragma unroll
            for (int hh = 0; hh < 2; hh++) {
                int rr = row0 + wm + 16 * t + 8 * hh + g;
                if (rr < M) {
                    float v0 = acc[t][j][hh * 2 + 0];
                    float v1 = acc[t][j][hh * 2 + 1];
                    if (BIAS) { v0 += bias[cc]; v1 += bias[cc + 1]; }
                    if (RELU) { v0 = fmaxf(v0, 0.f); v1 = fmaxf(v1, 0.f); }
                    *(float2*)(C + (size_t)rr * N + cc) = make_float2(v0, v1);
                }
            }
        }
    }
}

// ---------------- attention + aggregation (warp per dst node) --------------
__global__ void attn_kernel() {
    int node = blockIdx.x * (blockDim.x >> 5) + (threadIdx.x >> 5);
    if (node >= NN) return;
    int lane = threadIdx.x & 31;
    const float* qkv = g_t;
    float4 qv = ((const float4*)(qkv + (size_t)node * 384))[lane];
    float s = 0.f;
    float4 acc = make_float4(0.f, 0.f, 0.f, 0.f);
    int e0 = g_off[node], e1 = g_off[node + 1];
    int e = e0;
    for (; e + 2 <= e1; e += 2) {
        const float* b0p = qkv + (size_t)g_csr[e] * 384;
        const float* b1p = qkv + (size_t)g_csr[e + 1] * 384;
        float4 k0 = ((const float4*)(b0p + 128))[lane];
        float4 v0 = ((const float4*)(b0p + 256))[lane];
        float4 k1 = ((const float4*)(b1p + 128))[lane];
        float4 v1 = ((const float4*)(b1p + 256))[lane];
        float p0 = qv.x * k0.x + qv.y * k0.y + qv.z * k0.z + qv.w * k0.w;
        float p1 = qv.x * k1.x + qv.y * k1.y + qv.z * k1.z + qv.w * k1.w;
        p0 += __shfl_xor_sync(0xFFFFFFFFu, p0, 1);
        p0 += __shfl_xor_sync(0xFFFFFFFFu, p0, 2);
        p1 += __shfl_xor_sync(0xFFFFFFFFu, p1, 1);
        p1 += __shfl_xor_sync(0xFFFFFFFFu, p1, 2);
        float w0 = __expf(p0 * 0.25f);
        float w1 = __expf(p1 * 0.25f);
        s += w0 + w1;
        acc.x += w0 * v0.x + w1 * v1.x;
        acc.y += w0 * v0.y + w1 * v1.y;
        acc.z += w0 * v0.z + w1 * v1.z;
        acc.w += w0 * v0.w + w1 * v1.w;
    }
    if (e < e1) {
        const float* b0p = qkv + (size_t)g_csr[e] * 384;
        float4 k0 = ((const float4*)(b0p + 128))[lane];
        float4 v0 = ((const float4*)(b0p + 256))[lane];
        float p0 = qv.x * k0.x + qv.y * k0.y + qv.z * k0.z + qv.w * k0.w;
        p0 += __shfl_xor_sync(0xFFFFFFFFu, p0, 1);
        p0 += __shfl_xor_sync(0xFFFFFFFFu, p0, 2);
        float w0 = __expf(p0 * 0.25f);
        s += w0;
        acc.x += w0 * v0.x; acc.y += w0 * v0.y;
        acc.z += w0 * v0.z; acc.w += w0 * v0.w;
    }
    float inv = (s > 0.f) ? 1.f / s : 0.f;
    float4 o = make_float4(acc.x * inv, acc.y * inv, acc.z * inv, acc.w * inv);
    ((float4*)(g_agg + (size_t)node * DD))[lane] = o;
}

// ---------------- host-side launch -----------------------------------------
static inline void run_gemm(int bias, int relu, const float* A, const float* B,
                            const float* bp, float* C, int M, int N, int K) {
    dim3 grid((N + 127) / 128, (M + 127) / 128);
    if (bias && relu)
        tf32gemm_kernel<1, 1, 0><<<grid, 256, GEMM_SMEM_BYTES>>>(
            A, B, bp, C, M, N, K, nullptr, nullptr, nullptr);
    else if (bias)
        tf32gemm_kernel<1, 0, 0><<<grid, 256, GEMM_SMEM_BYTES>>>(
            A, B, bp, C, M, N, K, nullptr, nullptr, nullptr);
    else
        tf32gemm_kernel<0, 0, 0><<<grid, 256, GEMM_SMEM_BYTES>>>(
            A, B, bp, C, M, N, K, nullptr, nullptr, nullptr);
}

static inline void run_gemm256(int bias, int relu, const float* A, const float* B,
                               const float* bp, float* C, int M, int N, int K) {
    dim3 grid((N + 255) / 256, (M + 127) / 128);
    if (bias && relu)
        tf32gemm256_kernel<1, 1><<<grid, 256, G2_SMEM_BYTES>>>(A, B, bp, C, M, N, K);
    else
        tf32gemm256_kernel<0, 0><<<grid, 256, G2_SMEM_BYTES>>>(A, B, bp, C, M, N, K);
}

extern "C" void kernel_launch(void* const* d_in, const int* in_sizes, int n_in,
                              void* d_out, int out_size) {
    const float* X        = (const float*)d_in[0];
    const int*   ei       = (const int*)d_in[1];
    const float* emb_w    = (const float*)d_in[2];
    const float* emb_b    = (const float*)d_in[3];
    const float* emb_ln_g = (const float*)d_in[4];
    const float* emb_ln_b = (const float*)d_in[5];
    const float* Wq       = (const float*)d_in[6];
    const float* Wk       = (const float*)d_in[7];
    const float* Wv       = (const float*)d_in[8];
    const float* Wo       = (const float*)d_in[9];
    const float* ln_g     = (const float*)d_in[10];
    const float* ln_b     = (const float*)d_in[11];
    const float* f1_w     = (const float*)d_in[12];
    const float* f1_b     = (const float*)d_in[13];
    const float* f2_w     = (const float*)d_in[14];
    const float* f2_b     = (const float*)d_in[15];
    const float* f3_w     = (const float*)d_in[16];
    const float* f3_b     = (const float*)d_in[17];
    float* out = (float*)d_out;

    const int* src = ei;
    const int* dst = ei + EE;

    cudaFuncSetAttribute(tf32gemm_kernel<1, 1, 0>,
                         cudaFuncAttributeMaxDynamicSharedMemorySize, GEMM_SMEM_BYTES);
    cudaFuncSetAttribute(tf32gemm_kernel<1, 0, 0>,
                         cudaFuncAttributeMaxDynamicSharedMemorySize, GEMM_SMEM_BYTES);
    cudaFuncSetAttribute(tf32gemm_kernel<0, 0, 0>,
                         cudaFuncAttributeMaxDynamicSharedMemorySize, GEMM_SMEM_BYTES);
    cudaFuncSetAttribute(tf32gemm_kernel<1, 1, 1>,
                         cudaFuncAttributeMaxDynamicSharedMemorySize, GEMM_SMEM_BYTES);
    cudaFuncSetAttribute(tf32gemm_kernel<0, 0, 1>,
                         cudaFuncAttributeMaxDynamicSharedMemorySize, GEMM_SMEM_BYTES);
    cudaFuncSetAttribute(tf32gemm256_kernel<1, 1>,
                         cudaFuncAttributeMaxDynamicSharedMemorySize, G2_SMEM_BYTES);
    cudaFuncSetAttribute(tf32gemm256_kernel<0, 0>,
                         cudaFuncAttributeMaxDynamicSharedMemorySize, G2_SMEM_BYTES);

    float *p_h, *p_agg, *p_t, *p_t2, *p_wqkv;
    cudaGetSymbolAddress((void**)&p_h,    g_h);
    cudaGetSymbolAddress((void**)&p_agg,  g_agg);
    cudaGetSymbolAddress((void**)&p_t,    g_t);
    cudaGetSymbolAddress((void**)&p_t2,   g_t2);
    cudaGetSymbolAddress((void**)&p_wqkv, g_wqkv);

    // ---- CSR build (by dst) + weight packing ----
    zero_deg_kernel<<<(NN + 255) / 256, 256>>>();
    count_deg_kernel<<<(EE + 255) / 256, 256>>>(dst);
    scan_kernel<<<1, 1024>>>();
    scatter_kernel<<<(EE + 255) / 256, 256>>>(src, dst);
    pack_qkv_kernel<<<(LL * DD * DD + 255) / 256, 256>>>(Wq, Wk, Wv);

    // ---- embedding: LN(relu(X @ emb_w + b)) -> h, fused epilogue ----
    {
        dim3 grid(1, (NN + 127) / 128);
        tf32gemm_kernel<1, 1, 1><<<grid, 256, GEMM_SMEM_BYTES>>>(
            X, emb_w, emb_b, p_h, NN, DD, DIN, nullptr, emb_ln_g, emb_ln_b);
    }

    // ---- layers ----
    for (int l = 0; l < LL; l++) {
        const float* wo = Wo + (size_t)l * DD * DD;
        // fused qkv [N,384] via 64x64-tile kernel (overlapping col tiles)
        run_gemm256(0, 0, p_h, p_wqkv + (size_t)l * DD * 384, nullptr, p_t, NN, 384, DD);
        attn_kernel<<<(NN + 7) / 8, 256>>>();
        // h = LN(h + agg @ Wo), fused residual+LN epilogue (in-place on p_h)
        dim3 grid(1, (NN + 127) / 128);
        tf32gemm_kernel<0, 0, 1><<<grid, 256, GEMM_SMEM_BYTES>>>(
            p_agg, wo, nullptr, p_h, NN, DD, DD, p_h, ln_g + l * DD, ln_b + l * DD);
    }

    // ---- MLP head ----
    run_gemm256(1, 1, p_h,  f1_w, f1_b, p_t,  NN, 512, DD);
    run_gemm256(1, 1, p_t,  f2_w, f2_b, p_t2, NN, 512, 512);
    run_gemm(1, 0, p_t2, f3_w, f3_b, out,  NN, NCC, 512);
}

// round 15
// speedup vs baseline: 1.0789x; 1.0789x over previous
#include <cuda_runtime.h>
#include <math.h>
#include <math_constants.h>

#define NN 50000
#define EE 640000
#define DIN 256
#define DD 128
#define HH 8
#define NCC 47
#define LL 3

// ---------------- scratch (static device allocations; no runtime alloc) ----
__device__ float g_h[NN * DD];
__device__ float g_agg[NN * DD];
__device__ float g_t[NN * 512];       // qkv [N,384] per layer; also ff1 [N,512]
__device__ float g_t2[NN * 512];      // ff2 [N,512]
__device__ float g_wqkv[LL * DD * 384];
__device__ int   g_deg[NN];
__device__ int   g_off[NN + 1];
__device__ int   g_cur[NN];
__device__ int   g_csr[EE];

// ---------------- CSR build ------------------------------------------------
__global__ void zero_deg_kernel() {
    int i = blockIdx.x * blockDim.x + threadIdx.x;
    if (i < NN) g_deg[i] = 0;
}

__global__ void count_deg_kernel(const int* __restrict__ dst) {
    int e = blockIdx.x * blockDim.x + threadIdx.x;
    if (e < EE) atomicAdd(&g_deg[dst[e]], 1);
}

__global__ void scan_kernel() {
    __shared__ int wsum[32];
    __shared__ int carry_s;
    int t = threadIdx.x, lane = t & 31, wid = t >> 5;
    if (t == 0) carry_s = 0;
    __syncthreads();
    for (int base = 0; base < NN; base += 1024) {
        int i = base + t;
        int val = (i < NN) ? g_deg[i] : 0;
        int incl = val;
        #pragma unroll
        for (int o = 1; o < 32; o <<= 1) {
            int x = __shfl_up_sync(0xFFFFFFFFu, incl, o);
            if (lane >= o) incl += x;
        }
        if (lane == 31) wsum[wid] = incl;
        __syncthreads();
        if (wid == 0) {
            int wv = wsum[lane];
            int wincl = wv;
            #pragma unroll
            for (int o = 1; o < 32; o <<= 1) {
                int x = __shfl_up_sync(0xFFFFFFFFu, wincl, o);
                if (lane >= o) wincl += x;
            }
            wsum[lane] = wincl - wv;
        }
        __syncthreads();
        int carry = carry_s;
        int excl = carry + wsum[wid] + incl - val;
        if (i < NN) { g_off[i] = excl; g_cur[i] = excl; }
        __syncthreads();
        if (t == 1023) carry_s = carry + wsum[31] + incl;
        __syncthreads();
    }
    if (threadIdx.x == 0) g_off[NN] = carry_s;
}

__global__ void scatter_kernel(const int* __restrict__ src, const int* __restrict__ dst) {
    int e = blockIdx.x * blockDim.x + threadIdx.x;
    if (e < EE) {
        int d = dst[e];
        int pos = atomicAdd(&g_cur[d], 1);
        g_csr[pos] = src[e];
    }
}

// ---------------- pack Wq|Wk|Wv -> [L][128][384] ---------------------------
__global__ void pack_qkv_kernel(const float* __restrict__ Wq,
                                const float* __restrict__ Wk,
                                const float* __restrict__ Wv) {
    int i = blockIdx.x * blockDim.x + threadIdx.x;
    if (i < LL * DD * DD) {
        int l = i / (DD * DD);
        int r = (i / DD) % DD;
        int c = i % DD;
        size_t o = ((size_t)l * DD + r) * 384;
        g_wqkv[o + c]       = Wq[i];
        g_wqkv[o + 128 + c] = Wk[i];
        g_wqkv[o + 256 + c] = Wv[i];
    }
}

__device__ __forceinline__ unsigned f2tf(float f) {
    unsigned u;
    asm("cvt.rna.tf32.f32 %0, %1;" : "=r"(u) : "f"(f));
    return u;
}

#define MMA_TF32(d, a0, a1, a2, a3, b0, b1)                              \
    asm volatile(                                                        \
        "mma.sync.aligned.m16n8k8.row.col.f32.tf32.tf32.f32 "            \
        "{%0,%1,%2,%3}, {%4,%5,%6,%7}, {%8,%9}, {%0,%1,%2,%3};"          \
        : "+f"(d[0]), "+f"(d[1]), "+f"(d[2]), "+f"(d[3])                 \
        : "r"(a0), "r"(a1), "r"(a2), "r"(a3), "r"(b0), "r"(b1))

// ============ TF32 GEMM: BM=128,BN=128, 32x64 warp tile, 2 blocks/SM =======
// Double-buffered, padded [16][136] smem (conflict-free), LN-fusable epilogue.
// B staging vectorized: one STS.128 per 4 tf32 words (bRow warp-uniform,
// lane*4 contiguous -> conflict-free 128B stores).
#define GEMM_SMEM_BYTES (2 * 2 * 16 * 136 * 4)

template <int BIAS, int RELU, int LN>
__global__ void __launch_bounds__(256, 2)
tf32gemm_kernel(const float* __restrict__ A, const float* __restrict__ B,
                const float* __restrict__ bias, float* __restrict__ C,
                int M, int N, int K,
                const float* __restrict__ resid,
                const float* __restrict__ lngam,
                const float* __restrict__ lnbet) {
    extern __shared__ unsigned sm[];
    unsigned (*As)[16][136] = (unsigned (*)[16][136])sm;
    unsigned (*Bs)[16][136] = (unsigned (*)[16][136])(sm + 2 * 16 * 136);

    int tid = threadIdx.x, lane = tid & 31, wid = tid >> 5;
    int row0 = blockIdx.y * 128, col0 = blockIdx.x * 128;
    int wm = (wid & 3) * 32, wn = (wid >> 2) * 64;
    int g = lane >> 2, c = lane & 3;

    int aRow = tid >> 1, aSeg = tid & 1;
    int bRow = tid >> 5;
    int gr = row0 + aRow;
    int gc = col0 + lane * 4;

    const bool nVec = ((N & 127) == 0);
    const bool nEven = ((N & 1) == 0);

    float acc[2][8][4];
    #pragma unroll
    for (int i = 0; i < 2; i++)
        #pragma unroll
        for (int j = 0; j < 8; j++)
            #pragma unroll
            for (int r = 0; r < 4; r++) acc[i][j][r] = 0.f;

    float4 pa0, pa1, pb0, pb1;

    auto fetch = [&](int k0) {
        pa0 = make_float4(0.f, 0.f, 0.f, 0.f); pa1 = pa0;
        if (gr < M) {
            const float* ap = A + (size_t)gr * K + k0 + aSeg * 8;
            pa0 = ((const float4*)ap)[0];
            pa1 = ((const float4*)ap)[1];
        }
        const float* bp0 = B + (size_t)(k0 + bRow) * N + gc;
        const float* bp1 = B + (size_t)(k0 + bRow + 8) * N + gc;
        if (nVec) {
            pb0 = *(const float4*)bp0;
            pb1 = *(const float4*)bp1;
        } else {
            pb0.x = (gc + 0 < N) ? bp0[0] : 0.f;
            pb0.y = (gc + 1 < N) ? bp0[1] : 0.f;
            pb0.z = (gc + 2 < N) ? bp0[2] : 0.f;
            pb0.w = (gc + 3 < N) ? bp0[3] : 0.f;
            pb1.x = (gc + 0 < N) ? bp1[0] : 0.f;
            pb1.y = (gc + 1 < N) ? bp1[1] : 0.f;
            pb1.z = (gc + 2 < N) ? bp1[2] : 0.f;
            pb1.w = (gc + 3 < N) ? bp1[3] : 0.f;
        }
    };
    auto stage = [&](int s) {
        int kb = aSeg * 8;
        As[s][kb + 0][aRow] = f2tf(pa0.x);
        As[s][kb + 1][aRow] = f2tf(pa0.y);
        As[s][kb + 2][aRow] = f2tf(pa0.z);
        As[s][kb + 3][aRow] = f2tf(pa0.w);
        As[s][kb + 4][aRow] = f2tf(pa1.x);
        As[s][kb + 5][aRow] = f2tf(pa1.y);
        As[s][kb + 6][aRow] = f2tf(pa1.z);
        As[s][kb + 7][aRow] = f2tf(pa1.w);
        uint4 u0 = make_uint4(f2tf(pb0.x), f2tf(pb0.y), f2tf(pb0.z), f2tf(pb0.w));
        uint4 u1 = make_uint4(f2tf(pb1.x), f2tf(pb1.y), f2tf(pb1.z), f2tf(pb1.w));
        *(uint4*)&Bs[s][bRow][lane * 4]     = u0;
        *(uint4*)&Bs[s][bRow + 8][lane * 4] = u1;
    };

    fetch(0);
    stage(0);
    __syncthreads();

    int s = 0;
    for (int k0 = 0; k0 < K; k0 += 16) {
        bool hasNext = (k0 + 16) < K;
        if (hasNext) fetch(k0 + 16);

        #pragma unroll
        for (int ks = 0; ks < 2; ks++) {
            int kb = ks * 8;
            unsigned a[2][4];
            #pragma unroll
            for (int i = 0; i < 2; i++) {
                int m = wm + 16 * i + g;
                a[i][0] = As[s][kb + c][m];
                a[i][1] = As[s][kb + c][m + 8];
                a[i][2] = As[s][kb + c + 4][m];
                a[i][3] = As[s][kb + c + 4][m + 8];
            }
            #pragma unroll
            for (int j = 0; j < 8; j++) {
                unsigned b0 = Bs[s][kb + c][wn + 8 * j + g];
                unsigned b1 = Bs[s][kb + c + 4][wn + 8 * j + g];
                #pragma unroll
                for (int i = 0; i < 2; i++) {
                    MMA_TF32(acc[i][j], a[i][0], a[i][1], a[i][2], a[i][3], b0, b1);
                }
            }
        }

        if (hasNext) {
            stage(s ^ 1);
            __syncthreads();
            s ^= 1;
        }
    }

    if (LN) {
        // ---- fused LayerNorm epilogue (N==128, one block per 128 rows) ----
        __syncthreads();
        float* rsum = (float*)sm;
        float* rsq  = (float*)sm + 256;
        int half = wn >> 6;
        #pragma unroll
        for (int i = 0; i < 2; i++) {
            #pragma unroll
            for (int hh = 0; hh < 2; hh++) {
                int lr = wm + 16 * i + 8 * hh + g;
                int rr = row0 + lr;
                float s16 = 0.f, q16 = 0.f;
                #pragma unroll
                for (int j = 0; j < 8; j++) {
                    int cc = wn + 8 * j + 2 * c;
                    float v0 = acc[i][j][2 * hh + 0];
                    float v1 = acc[i][j][2 * hh + 1];
                    if (BIAS) { v0 += bias[cc]; v1 += bias[cc + 1]; }
                    if (RELU) { v0 = fmaxf(v0, 0.f); v1 = fmaxf(v1, 0.f); }
                    if (resid != nullptr && rr < M) {
                        float2 rv = *(const float2*)(resid + (size_t)rr * 128 + cc);
                        v0 += rv.x; v1 += rv.y;
                    }
                    acc[i][j][2 * hh + 0] = v0;
                    acc[i][j][2 * hh + 1] = v1;
                    s16 += v0 + v1;
                    q16 += v0 * v0 + v1 * v1;
                }
                s16 += __shfl_xor_sync(0xFFFFFFFFu, s16, 1);
                s16 += __shfl_xor_sync(0xFFFFFFFFu, s16, 2);
                q16 += __shfl_xor_sync(0xFFFFFFFFu, q16, 1);
                q16 += __shfl_xor_sync(0xFFFFFFFFu, q16, 2);
                if (c == 0) {
                    rsum[half * 128 + lr] = s16;
                    rsq [half * 128 + lr] = q16;
                }
            }
        }
        __syncthreads();
        #pragma unroll
        for (int i = 0; i < 2; i++) {
            #pragma unroll
            for (int hh = 0; hh < 2; hh++) {
                int lr = wm + 16 * i + 8 * hh + g;
                int rr = row0 + lr;
                if (rr >= M) continue;
                float tot = rsum[lr] + rsum[128 + lr];
                float tq  = rsq[lr]  + rsq[128 + lr];
                float mu  = tot * (1.f / 128.f);
                float var = tq * (1.f / 128.f) - mu * mu;
                float rstd = rsqrtf(var + 1e-5f);
                #pragma unroll
                for (int j = 0; j < 8; j++) {
                    int cc = wn + 8 * j + 2 * c;
                    float2 gg = *(const float2*)(lngam + cc);
                    float2 bb = *(const float2*)(lnbet + cc);
                    float y0 = (acc[i][j][2 * hh + 0] - mu) * rstd * gg.x + bb.x;
                    float y1 = (acc[i][j][2 * hh + 1] - mu) * rstd * gg.y + bb.y;
                    *(float2*)(C + (size_t)rr * 128 + cc) = make_float2(y0, y1);
                }
            }
        }
        return;
    }

    // ---- plain epilogue ----
    #pragma unroll
    for (int i = 0; i < 2; i++) {
        int r = row0 + wm + 16 * i + g;
        #pragma unroll
        for (int j = 0; j < 8; j++) {
            int cc = col0 + wn + 8 * j + 2 * c;
            #pragma unroll
            for (int hh = 0; hh < 2; hh++) {
                int rr = r + hh * 8;
                if (rr < M) {
                    float v0 = acc[i][j][hh * 2 + 0];
                    float v1 = acc[i][j][hh * 2 + 1];
                    float* cp = C + (size_t)rr * N + cc;
                    if (nEven) {
                        if (cc + 1 < N) {
                            if (BIAS) { v0 += bias[cc]; v1 += bias[cc + 1]; }
                            if (RELU) { v0 = fmaxf(v0, 0.f); v1 = fmaxf(v1, 0.f); }
                            *(float2*)cp = make_float2(v0, v1);
                        } else if (cc < N) {
                            if (BIAS) v0 += bias[cc];
                            if (RELU) v0 = fmaxf(v0, 0.f);
                            cp[0] = v0;
                        }
                    } else {
                        if (cc < N) {
                            if (BIAS) v0 += bias[cc];
                            if (RELU) v0 = fmaxf(v0, 0.f);
                            cp[0] = v0;
                        }
                        if (cc + 1 < N) {
                            if (BIAS) v1 += bias[cc + 1];
                            if (RELU) v1 = fmaxf(v1, 0.f);
                            cp[1] = v1;
                        }
                    }
                }
            }
        }
    }
}

// ---------------- attention + aggregation (warp per dst node) --------------
// qkv interleaved [node][384]: q 0-127, k 128-255, v 256-383.
// 4-edge unroll: 8 independent 16B gathers in flight per iteration.
__global__ void attn_kernel() {
    int node = blockIdx.x * (blockDim.x >> 5) + (threadIdx.x >> 5);
    if (node >= NN) return;
    int lane = threadIdx.x & 31;
    const float* qkv = g_t;
    float4 qv = ((const float4*)(qkv + (size_t)node * 384))[lane];
    float s = 0.f;
    float4 acc = make_float4(0.f, 0.f, 0.f, 0.f);
    int e0 = g_off[node], e1 = g_off[node + 1];
    int e = e0;
    for (; e + 4 <= e1; e += 4) {
        const float* p0 = qkv + (size_t)g_csr[e + 0] * 384;
        const float* p1 = qkv + (size_t)g_csr[e + 1] * 384;
        const float* p2 = qkv + (size_t)g_csr[e + 2] * 384;
        const float* p3 = qkv + (size_t)g_csr[e + 3] * 384;
        float4 k0 = ((const float4*)(p0 + 128))[lane];
        float4 k1 = ((const float4*)(p1 + 128))[lane];
        float4 k2 = ((const float4*)(p2 + 128))[lane];
        float4 k3 = ((const float4*)(p3 + 128))[lane];
        float4 v0 = ((const float4*)(p0 + 256))[lane];
        float4 v1 = ((const float4*)(p1 + 256))[lane];
        float4 v2 = ((const float4*)(p2 + 256))[lane];
        float4 v3 = ((const float4*)(p3 + 256))[lane];
        float d0 = qv.x * k0.x + qv.y * k0.y + qv.z * k0.z + qv.w * k0.w;
        float d1 = qv.x * k1.x + qv.y * k1.y + qv.z * k1.z + qv.w * k1.w;
        float d2 = qv.x * k2.x + qv.y * k2.y + qv.z * k2.z + qv.w * k2.w;
        float d3 = qv.x * k3.x + qv.y * k3.y + qv.z * k3.z + qv.w * k3.w;
        d0 += __shfl_xor_sync(0xFFFFFFFFu, d0, 1);
        d0 += __shfl_xor_sync(0xFFFFFFFFu, d0, 2);
        d1 += __shfl_xor_sync(0xFFFFFFFFu, d1, 1);
        d1 += __shfl_xor_sync(0xFFFFFFFFu, d1, 2);
        d2 += __shfl_xor_sync(0xFFFFFFFFu, d2, 1);
        d2 += __shfl_xor_sync(0xFFFFFFFFu, d2, 2);
        d3 += __shfl_xor_sync(0xFFFFFFFFu, d3, 1);
        d3 += __shfl_xor_sync(0xFFFFFFFFu, d3, 2);
        float w0 = __expf(d0 * 0.25f);
        float w1 = __expf(d1 * 0.25f);
        float w2 = __expf(d2 * 0.25f);
        float w3 = __expf(d3 * 0.25f);
        s += (w0 + w1) + (w2 + w3);
        acc.x += w0 * v0.x + w1 * v1.x + w2 * v2.x + w3 * v3.x;
        acc.y += w0 * v0.y + w1 * v1.y + w2 * v2.y + w3 * v3.y;
        acc.z += w0 * v0.z + w1 * v1.z + w2 * v2.z + w3 * v3.z;
        acc.w += w0 * v0.w + w1 * v1.w + w2 * v2.w + w3 * v3.w;
    }
    for (; e < e1; e++) {
        const float* p0 = qkv + (size_t)g_csr[e] * 384;
        float4 k0 = ((const float4*)(p0 + 128))[lane];
        float4 v0 = ((const float4*)(p0 + 256))[lane];
        float d0 = qv.x * k0.x + qv.y * k0.y + qv.z * k0.z + qv.w * k0.w;
        d0 += __shfl_xor_sync(0xFFFFFFFFu, d0, 1);
        d0 += __shfl_xor_sync(0xFFFFFFFFu, d0, 2);
        float w0 = __expf(d0 * 0.25f);
        s += w0;
        acc.x += w0 * v0.x; acc.y += w0 * v0.y;
        acc.z += w0 * v0.z; acc.w += w0 * v0.w;
    }
    float inv = (s > 0.f) ? 1.f / s : 0.f;
    float4 o = make_float4(acc.x * inv, acc.y * inv, acc.z * inv, acc.w * inv);
    ((float4*)(g_agg + (size_t)node * DD))[lane] = o;
}

// ---------------- host-side launch -----------------------------------------
static inline void run_gemm(int bias, int relu, const float* A, const float* B,
                            const float* bp, float* C, int M, int N, int K) {
    dim3 grid((N + 127) / 128, (M + 127) / 128);
    if (bias && relu)
        tf32gemm_kernel<1, 1, 0><<<grid, 256, GEMM_SMEM_BYTES>>>(
            A, B, bp, C, M, N, K, nullptr, nullptr, nullptr);
    else if (bias)
        tf32gemm_kernel<1, 0, 0><<<grid, 256, GEMM_SMEM_BYTES>>>(
            A, B, bp, C, M, N, K, nullptr, nullptr, nullptr);
    else
        tf32gemm_kernel<0, 0, 0><<<grid, 256, GEMM_SMEM_BYTES>>>(
            A, B, bp, C, M, N, K, nullptr, nullptr, nullptr);
}

extern "C" void kernel_launch(void* const* d_in, const int* in_sizes, int n_in,
                              void* d_out, int out_size) {
    const float* X        = (const float*)d_in[0];
    const int*   ei       = (const int*)d_in[1];
    const float* emb_w    = (const float*)d_in[2];
    const float* emb_b    = (const float*)d_in[3];
    const float* emb_ln_g = (const float*)d_in[4];
    const float* emb_ln_b = (const float*)d_in[5];
    const float* Wq       = (const float*)d_in[6];
    const float* Wk       = (const float*)d_in[7];
    const float* Wv       = (const float*)d_in[8];
    const float* Wo       = (const float*)d_in[9];
    const float* ln_g     = (const float*)d_in[10];
    const float* ln_b     = (const float*)d_in[11];
    const float* f1_w     = (const float*)d_in[12];
    const float* f1_b     = (const float*)d_in[13];
    const float* f2_w     = (const float*)d_in[14];
    const float* f2_b     = (const float*)d_in[15];
    const float* f3_w     = (const float*)d_in[16];
    const float* f3_b     = (const float*)d_in[17];
    float* out = (float*)d_out;

    const int* src = ei;
    const int* dst = ei + EE;

    cudaFuncSetAttribute(tf32gemm_kernel<1, 1, 0>,
                         cudaFuncAttributeMaxDynamicSharedMemorySize, GEMM_SMEM_BYTES);
    cudaFuncSetAttribute(tf32gemm_kernel<1, 0, 0>,
                         cudaFuncAttributeMaxDynamicSharedMemorySize, GEMM_SMEM_BYTES);
    cudaFuncSetAttribute(tf32gemm_kernel<0, 0, 0>,
                         cudaFuncAttributeMaxDynamicSharedMemorySize, GEMM_SMEM_BYTES);
    cudaFuncSetAttribute(tf32gemm_kernel<1, 1, 1>,
                         cudaFuncAttributeMaxDynamicSharedMemorySize, GEMM_SMEM_BYTES);
    cudaFuncSetAttribute(tf32gemm_kernel<0, 0, 1>,
                         cudaFuncAttributeMaxDynamicSharedMemorySize, GEMM_SMEM_BYTES);

    float *p_h, *p_agg, *p_t, *p_t2, *p_wqkv;
    cudaGetSymbolAddress((void**)&p_h,    g_h);
    cudaGetSymbolAddress((void**)&p_agg,  g_agg);
    cudaGetSymbolAddress((void**)&p_t,    g_t);
    cudaGetSymbolAddress((void**)&p_t2,   g_t2);
    cudaGetSymbolAddress((void**)&p_wqkv, g_wqkv);

    // ---- CSR build (by dst) + weight packing ----
    zero_deg_kernel<<<(NN + 255) / 256, 256>>>();
    count_deg_kernel<<<(EE + 255) / 256, 256>>>(dst);
    scan_kernel<<<1, 1024>>>();
    scatter_kernel<<<(EE + 255) / 256, 256>>>(src, dst);
    pack_qkv_kernel<<<(LL * DD * DD + 255) / 256, 256>>>(Wq, Wk, Wv);

    // ---- embedding: LN(relu(X @ emb_w + b)) -> h, fused epilogue ----
    {
        dim3 grid(1, (NN + 127) / 128);
        tf32gemm_kernel<1, 1, 1><<<grid, 256, GEMM_SMEM_BYTES>>>(
            X, emb_w, emb_b, p_h, NN, DD, DIN, nullptr, emb_ln_g, emb_ln_b);
    }

    // ---- layers ----
    for (int l = 0; l < LL; l++) {
        const float* wo = Wo + (size_t)l * DD * DD;
        // fused qkv: [N,384] interleaved
        run_gemm(0, 0, p_h, p_wqkv + (size_t)l * DD * 384, nullptr, p_t, NN, 384, DD);
        attn_kernel<<<(NN + 7) / 8, 256>>>();
        // h = LN(h + agg @ Wo), fused residual+LN epilogue (in-place on p_h)
        dim3 grid(1, (NN + 127) / 128);
        tf32gemm_kernel<0, 0, 1><<<grid, 256, GEMM_SMEM_BYTES>>>(
            p_agg, wo, nullptr, p_h, NN, DD, DD, p_h, ln_g + l * DD, ln_b + l * DD);
    }

    // ---- MLP head ----
    run_gemm(1, 1, p_h,  f1_w, f1_b, p_t,  NN, 512, DD);
    run_gemm(1, 1, p_t,  f2_w, f2_b, p_t2, NN, 512, 512);
    run_gemm(1, 0, p_t2, f3_w, f3_b, out,  NN, NCC, 512);
}

// round 16
// speedup vs baseline: 1.1000x; 1.0195x over previous
#include <cuda_runtime.h>
#include <cuda_fp16.h>
#include <math.h>
#include <math_constants.h>

#define NN 50000
#define EE 640000
#define DIN 256
#define DD 128
#define HH 8
#define NCC 47
#define LL 3

// ---------------- scratch (static device allocations; no runtime alloc) ----
__device__ float  g_h[NN * DD];
__device__ float  g_agg[NN * DD];
__device__ float  g_t[NN * 512];      // q [N,128] per layer; also ff1 [N,512]
__device__ float  g_t2[NN * 512];     // ff2 [N,512]
__device__ __half g_kv[NN * 256];     // k [0..127] + v [128..255] per node, fp16
__device__ float  g_wqkv[LL * DD * 384];
__device__ int    g_deg[NN];
__device__ int    g_off[NN + 1];
__device__ int    g_cur[NN];
__device__ int    g_csr[EE];

// ---------------- CSR build ------------------------------------------------
__global__ void zero_deg_kernel() {
    int i = blockIdx.x * blockDim.x + threadIdx.x;
    if (i < NN) g_deg[i] = 0;
}

__global__ void count_deg_kernel(const int* __restrict__ dst) {
    int e = blockIdx.x * blockDim.x + threadIdx.x;
    if (e < EE) atomicAdd(&g_deg[dst[e]], 1);
}

__global__ void scan_kernel() {
    __shared__ int wsum[32];
    __shared__ int carry_s;
    int t = threadIdx.x, lane = t & 31, wid = t >> 5;
    if (t == 0) carry_s = 0;
    __syncthreads();
    for (int base = 0; base < NN; base += 1024) {
        int i = base + t;
        int val = (i < NN) ? g_deg[i] : 0;
        int incl = val;
        #pragma unroll
        for (int o = 1; o < 32; o <<= 1) {
            int x = __shfl_up_sync(0xFFFFFFFFu, incl, o);
            if (lane >= o) incl += x;
        }
        if (lane == 31) wsum[wid] = incl;
        __syncthreads();
        if (wid == 0) {
            int wv = wsum[lane];
            int wincl = wv;
            #pragma unroll
            for (int o = 1; o < 32; o <<= 1) {
                int x = __shfl_up_sync(0xFFFFFFFFu, wincl, o);
                if (lane >= o) wincl += x;
            }
            wsum[lane] = wincl - wv;
        }
        __syncthreads();
        int carry = carry_s;
        int excl = carry + wsum[wid] + incl - val;
        if (i < NN) { g_off[i] = excl; g_cur[i] = excl; }
        __syncthreads();
        if (t == 1023) carry_s = carry + wsum[31] + incl;
        __syncthreads();
    }
    if (threadIdx.x == 0) g_off[NN] = carry_s;
}

__global__ void scatter_kernel(const int* __restrict__ src, const int* __restrict__ dst) {
    int e = blockIdx.x * blockDim.x + threadIdx.x;
    if (e < EE) {
        int d = dst[e];
        int pos = atomicAdd(&g_cur[d], 1);
        g_csr[pos] = src[e];
    }
}

// ---------------- pack Wq|Wk|Wv -> [L][128][384] ---------------------------
__global__ void pack_qkv_kernel(const float* __restrict__ Wq,
                                const float* __restrict__ Wk,
                                const float* __restrict__ Wv) {
    int i = blockIdx.x * blockDim.x + threadIdx.x;
    if (i < LL * DD * DD) {
        int l = i / (DD * DD);
        int r = (i / DD) % DD;
        int c = i % DD;
        size_t o = ((size_t)l * DD + r) * 384;
        g_wqkv[o + c]       = Wq[i];
        g_wqkv[o + 128 + c] = Wk[i];
        g_wqkv[o + 256 + c] = Wv[i];
    }
}

__device__ __forceinline__ unsigned f2tf(float f) {
    unsigned u;
    asm("cvt.rna.tf32.f32 %0, %1;" : "=r"(u) : "f"(f));
    return u;
}

#define MMA_TF32(d, a0, a1, a2, a3, b0, b1)                              \
    asm volatile(                                                        \
        "mma.sync.aligned.m16n8k8.row.col.f32.tf32.tf32.f32 "            \
        "{%0,%1,%2,%3}, {%4,%5,%6,%7}, {%8,%9}, {%0,%1,%2,%3};"          \
        : "+f"(d[0]), "+f"(d[1]), "+f"(d[2]), "+f"(d[3])                 \
        : "r"(a0), "r"(a1), "r"(a2), "r"(a3), "r"(b0), "r"(b1))

// ============ TF32 GEMM: BM=128,BN=128, 32x64 warp tile, 2 blocks/SM =======
// LN=1: fused LayerNorm epilogue (N==128, grid.x==1), optional residual.
// QKV=1: cols [0,128) -> fp32 C[rr*128+..] (q); cols [128,384) -> fp16
//        kvout[rr*256 + (cc-128)] (k then v). Used with N=384.
#define GEMM_SMEM_BYTES (2 * 2 * 16 * 136 * 4)

template <int BIAS, int RELU, int LN, int QKV>
__global__ void __launch_bounds__(256, 2)
tf32gemm_kernel(const float* __restrict__ A, const float* __restrict__ B,
                const float* __restrict__ bias, float* __restrict__ C,
                int M, int N, int K,
                const float* __restrict__ resid,
                const float* __restrict__ lngam,
                const float* __restrict__ lnbet,
                __half* __restrict__ kvout) {
    extern __shared__ unsigned sm[];
    unsigned (*As)[16][136] = (unsigned (*)[16][136])sm;
    unsigned (*Bs)[16][136] = (unsigned (*)[16][136])(sm + 2 * 16 * 136);

    int tid = threadIdx.x, lane = tid & 31, wid = tid >> 5;
    int row0 = blockIdx.y * 128, col0 = blockIdx.x * 128;
    int wm = (wid & 3) * 32, wn = (wid >> 2) * 64;
    int g = lane >> 2, c = lane & 3;

    int aRow = tid >> 1, aSeg = tid & 1;
    int bRow = tid >> 5;
    int gr = row0 + aRow;
    int gc = col0 + lane * 4;

    const bool nVec = ((N & 127) == 0);
    const bool nEven = ((N & 1) == 0);

    float acc[2][8][4];
    #pragma unroll
    for (int i = 0; i < 2; i++)
        #pragma unroll
        for (int j = 0; j < 8; j++)
            #pragma unroll
            for (int r = 0; r < 4; r++) acc[i][j][r] = 0.f;

    float4 pa0, pa1, pb0, pb1;

    auto fetch = [&](int k0) {
        pa0 = make_float4(0.f, 0.f, 0.f, 0.f); pa1 = pa0;
        if (gr < M) {
            const float* ap = A + (size_t)gr * K + k0 + aSeg * 8;
            pa0 = ((const float4*)ap)[0];
            pa1 = ((const float4*)ap)[1];
        }
        const float* bp0 = B + (size_t)(k0 + bRow) * N + gc;
        const float* bp1 = B + (size_t)(k0 + bRow + 8) * N + gc;
        if (nVec) {
            pb0 = *(const float4*)bp0;
            pb1 = *(const float4*)bp1;
        } else {
            pb0.x = (gc + 0 < N) ? bp0[0] : 0.f;
            pb0.y = (gc + 1 < N) ? bp0[1] : 0.f;
            pb0.z = (gc + 2 < N) ? bp0[2] : 0.f;
            pb0.w = (gc + 3 < N) ? bp0[3] : 0.f;
            pb1.x = (gc + 0 < N) ? bp1[0] : 0.f;
            pb1.y = (gc + 1 < N) ? bp1[1] : 0.f;
            pb1.z = (gc + 2 < N) ? bp1[2] : 0.f;
            pb1.w = (gc + 3 < N) ? bp1[3] : 0.f;
        }
    };
    auto stage = [&](int s) {
        int kb = aSeg * 8;
        As[s][kb + 0][aRow] = f2tf(pa0.x);
        As[s][kb + 1][aRow] = f2tf(pa0.y);
        As[s][kb + 2][aRow] = f2tf(pa0.z);
        As[s][kb + 3][aRow] = f2tf(pa0.w);
        As[s][kb + 4][aRow] = f2tf(pa1.x);
        As[s][kb + 5][aRow] = f2tf(pa1.y);
        As[s][kb + 6][aRow] = f2tf(pa1.z);
        As[s][kb + 7][aRow] = f2tf(pa1.w);
        uint4 u0 = make_uint4(f2tf(pb0.x), f2tf(pb0.y), f2tf(pb0.z), f2tf(pb0.w));
        uint4 u1 = make_uint4(f2tf(pb1.x), f2tf(pb1.y), f2tf(pb1.z), f2tf(pb1.w));
        *(uint4*)&Bs[s][bRow][lane * 4]     = u0;
        *(uint4*)&Bs[s][bRow + 8][lane * 4] = u1;
    };

    fetch(0);
    stage(0);
    __syncthreads();

    int s = 0;
    for (int k0 = 0; k0 < K; k0 += 16) {
        bool hasNext = (k0 + 16) < K;
        if (hasNext) fetch(k0 + 16);

        #pragma unroll
        for (int ks = 0; ks < 2; ks++) {
            int kb = ks * 8;
            unsigned a[2][4];
            #pragma unroll
            for (int i = 0; i < 2; i++) {
                int m = wm + 16 * i + g;
                a[i][0] = As[s][kb + c][m];
                a[i][1] = As[s][kb + c][m + 8];
                a[i][2] = As[s][kb + c + 4][m];
                a[i][3] = As[s][kb + c + 4][m + 8];
            }
            #pragma unroll
            for (int j = 0; j < 8; j++) {
                unsigned b0 = Bs[s][kb + c][wn + 8 * j + g];
                unsigned b1 = Bs[s][kb + c + 4][wn + 8 * j + g];
                #pragma unroll
                for (int i = 0; i < 2; i++) {
                    MMA_TF32(acc[i][j], a[i][0], a[i][1], a[i][2], a[i][3], b0, b1);
                }
            }
        }

        if (hasNext) {
            stage(s ^ 1);
            __syncthreads();
            s ^= 1;
        }
    }

    if (LN) {
        // ---- fused LayerNorm epilogue (N==128, one block per 128 rows) ----
        __syncthreads();
        float* rsum = (float*)sm;
        float* rsq  = (float*)sm + 256;
        int half_ = wn >> 6;
        #pragma unroll
        for (int i = 0; i < 2; i++) {
            #pragma unroll
            for (int hh = 0; hh < 2; hh++) {
                int lr = wm + 16 * i + 8 * hh + g;
                int rr = row0 + lr;
                float s16 = 0.f, q16 = 0.f;
                #pragma unroll
                for (int j = 0; j < 8; j++) {
                    int cc = wn + 8 * j + 2 * c;
                    float v0 = acc[i][j][2 * hh + 0];
                    float v1 = acc[i][j][2 * hh + 1];
                    if (BIAS) { v0 += bias[cc]; v1 += bias[cc + 1]; }
                    if (RELU) { v0 = fmaxf(v0, 0.f); v1 = fmaxf(v1, 0.f); }
                    if (resid != nullptr && rr < M) {
                        float2 rv = *(const float2*)(resid + (size_t)rr * 128 + cc);
                        v0 += rv.x; v1 += rv.y;
                    }
                    acc[i][j][2 * hh + 0] = v0;
                    acc[i][j][2 * hh + 1] = v1;
                    s16 += v0 + v1;
                    q16 += v0 * v0 + v1 * v1;
                }
                s16 += __shfl_xor_sync(0xFFFFFFFFu, s16, 1);
                s16 += __shfl_xor_sync(0xFFFFFFFFu, s16, 2);
                q16 += __shfl_xor_sync(0xFFFFFFFFu, q16, 1);
                q16 += __shfl_xor_sync(0xFFFFFFFFu, q16, 2);
                if (c == 0) {
                    rsum[half_ * 128 + lr] = s16;
                    rsq [half_ * 128 + lr] = q16;
                }
            }
        }
        __syncthreads();
        #pragma unroll
        for (int i = 0; i < 2; i++) {
            #pragma unroll
            for (int hh = 0; hh < 2; hh++) {
                int lr = wm + 16 * i + 8 * hh + g;
                int rr = row0 + lr;
                if (rr >= M) continue;
                float tot = rsum[lr] + rsum[128 + lr];
                float tq  = rsq[lr]  + rsq[128 + lr];
                float mu  = tot * (1.f / 128.f);
                float var = tq * (1.f / 128.f) - mu * mu;
                float rstd = rsqrtf(var + 1e-5f);
                #pragma unroll
                for (int j = 0; j < 8; j++) {
                    int cc = wn + 8 * j + 2 * c;
                    float2 gg = *(const float2*)(lngam + cc);
                    float2 bb = *(const float2*)(lnbet + cc);
                    float y0 = (acc[i][j][2 * hh + 0] - mu) * rstd * gg.x + bb.x;
                    float y1 = (acc[i][j][2 * hh + 1] - mu) * rstd * gg.y + bb.y;
                    *(float2*)(C + (size_t)rr * 128 + cc) = make_float2(y0, y1);
                }
            }
        }
        return;
    }

    if (QKV) {
        // ---- qkv epilogue: q fp32 [N,128], k/v fp16 packed [N,256] ----
        #pragma unroll
        for (int i = 0; i < 2; i++) {
            int r = row0 + wm + 16 * i + g;
            #pragma unroll
            for (int j = 0; j < 8; j++) {
                int cc = col0 + wn + 8 * j + 2 * c;
                #pragma unroll
                for (int hh = 0; hh < 2; hh++) {
                    int rr = r + hh * 8;
                    if (rr < M) {
                        float v0 = acc[i][j][hh * 2 + 0];
                        float v1 = acc[i][j][hh * 2 + 1];
                        if (cc < 128) {
                            *(float2*)(C + (size_t)rr * 128 + cc) = make_float2(v0, v1);
                        } else {
                            __half2 hv = __floats2half2_rn(v0, v1);
                            *(__half2*)(kvout + (size_t)rr * 256 + (cc - 128)) = hv;
                        }
                    }
                }
            }
        }
        return;
    }

    // ---- plain epilogue ----
    #pragma unroll
    for (int i = 0; i < 2; i++) {
        int r = row0 + wm + 16 * i + g;
        #pragma unroll
        for (int j = 0; j < 8; j++) {
            int cc = col0 + wn + 8 * j + 2 * c;
            #pragma unroll
            for (int hh = 0; hh < 2; hh++) {
                int rr = r + hh * 8;
                if (rr < M) {
                    float v0 = acc[i][j][hh * 2 + 0];
                    float v1 = acc[i][j][hh * 2 + 1];
                    float* cp = C + (size_t)rr * N + cc;
                    if (nEven) {
                        if (cc + 1 < N) {
                            if (BIAS) { v0 += bias[cc]; v1 += bias[cc + 1]; }
                            if (RELU) { v0 = fmaxf(v0, 0.f); v1 = fmaxf(v1, 0.f); }
                            *(float2*)cp = make_float2(v0, v1);
                        } else if (cc < N) {
                            if (BIAS) v0 += bias[cc];
                            if (RELU) v0 = fmaxf(v0, 0.f);
                            cp[0] = v0;
                        }
                    } else {
                        if (cc < N) {
                            if (BIAS) v0 += bias[cc];
                            if (RELU) v0 = fmaxf(v0, 0.f);
                            cp[0] = v0;
                        }
                        if (cc + 1 < N) {
                            if (BIAS) v1 += bias[cc + 1];
                            if (RELU) v1 = fmaxf(v1, 0.f);
                            cp[1] = v1;
                        }
                    }
                }
            }
        }
    }
}

// ---------------- attention + aggregation (warp per dst node) --------------
// q fp32 [node][128]; k/v fp16 packed [node][256] (k 0-127, v 128-255).
// 4-edge unroll: 8 independent 8B gathers in flight; half the L2 traffic.
__device__ __forceinline__ float dot4h(const float4& q, uint2 ku) {
    float2 a = __half22float2(*(__half2*)&ku.x);
    float2 b = __half22float2(*(__half2*)&ku.y);
    return q.x * a.x + q.y * a.y + q.z * b.x + q.w * b.y;
}

__global__ void attn_kernel() {
    int node = blockIdx.x * (blockDim.x >> 5) + (threadIdx.x >> 5);
    if (node >= NN) return;
    int lane = threadIdx.x & 31;
    float4 qv = ((const float4*)(g_t + (size_t)node * 128))[lane];
    float s = 0.f;
    float4 acc = make_float4(0.f, 0.f, 0.f, 0.f);
    int e0 = g_off[node], e1 = g_off[node + 1];
    int e = e0;
    for (; e + 4 <= e1; e += 4) {
        const __half* b0 = g_kv + (size_t)g_csr[e + 0] * 256;
        const __half* b1 = g_kv + (size_t)g_csr[e + 1] * 256;
        const __half* b2 = g_kv + (size_t)g_csr[e + 2] * 256;
        const __half* b3 = g_kv + (size_t)g_csr[e + 3] * 256;
        uint2 k0 = ((const uint2*)b0)[lane];
        uint2 k1 = ((const uint2*)b1)[lane];
        uint2 k2 = ((const uint2*)b2)[lane];
        uint2 k3 = ((const uint2*)b3)[lane];
        uint2 v0 = ((const uint2*)(b0 + 128))[lane];
        uint2 v1 = ((const uint2*)(b1 + 128))[lane];
        uint2 v2 = ((const uint2*)(b2 + 128))[lane];
        uint2 v3 = ((const uint2*)(b3 + 128))[lane];
        float d0 = dot4h(qv, k0);
        float d1 = dot4h(qv, k1);
        float d2 = dot4h(qv, k2);
        float d3 = dot4h(qv, k3);
        d0 += __shfl_xor_sync(0xFFFFFFFFu, d0, 1);
        d0 += __shfl_xor_sync(0xFFFFFFFFu, d0, 2);
        d1 += __shfl_xor_sync(0xFFFFFFFFu, d1, 1);
        d1 += __shfl_xor_sync(0xFFFFFFFFu, d1, 2);
        d2 += __shfl_xor_sync(0xFFFFFFFFu, d2, 1);
        d2 += __shfl_xor_sync(0xFFFFFFFFu, d2, 2);
        d3 += __shfl_xor_sync(0xFFFFFFFFu, d3, 1);
        d3 += __shfl_xor_sync(0xFFFFFFFFu, d3, 2);
        float w0 = __expf(d0 * 0.25f);
        float w1 = __expf(d1 * 0.25f);
        float w2 = __expf(d2 * 0.25f);
        float w3 = __expf(d3 * 0.25f);
        s += (w0 + w1) + (w2 + w3);
        float2 a0 = __half22float2(*(__half2*)&v0.x), c0 = __half22float2(*(__half2*)&v0.y);
        float2 a1 = __half22float2(*(__half2*)&v1.x), c1 = __half22float2(*(__half2*)&v1.y);
        float2 a2 = __half22float2(*(__half2*)&v2.x), c2 = __half22float2(*(__half2*)&v2.y);
        float2 a3 = __half22float2(*(__half2*)&v3.x), c3 = __half22float2(*(__half2*)&v3.y);
        acc.x += w0 * a0.x + w1 * a1.x + w2 * a2.x + w3 * a3.x;
        acc.y += w0 * a0.y + w1 * a1.y + w2 * a2.y + w3 * a3.y;
        acc.z += w0 * c0.x + w1 * c1.x + w2 * c2.x + w3 * c3.x;
        acc.w += w0 * c0.y + w1 * c1.y + w2 * c2.y + w3 * c3.y;
    }
    for (; e < e1; e++) {
        const __half* b0 = g_kv + (size_t)g_csr[e] * 256;
        uint2 k0 = ((const uint2*)b0)[lane];
        uint2 v0 = ((const uint2*)(b0 + 128))[lane];
        float d0 = dot4h(qv, k0);
        d0 += __shfl_xor_sync(0xFFFFFFFFu, d0, 1);
        d0 += __shfl_xor_sync(0xFFFFFFFFu, d0, 2);
        float w0 = __expf(d0 * 0.25f);
        s += w0;
        float2 a0 = __half22float2(*(__half2*)&v0.x), c0 = __half22float2(*(__half2*)&v0.y);
        acc.x += w0 * a0.x; acc.y += w0 * a0.y;
        acc.z += w0 * c0.x; acc.w += w0 * c0.y;
    }
    float inv = (s > 0.f) ? 1.f / s : 0.f;
    float4 o = make_float4(acc.x * inv, acc.y * inv, acc.z * inv, acc.w * inv);
    ((float4*)(g_agg + (size_t)node * DD))[lane] = o;
}

// ---------------- host-side launch -----------------------------------------
static inline void run_gemm(int bias, int relu, const float* A, const float* B,
                            const float* bp, float* C, int M, int N, int K) {
    dim3 grid((N + 127) / 128, (M + 127) / 128);
    if (bias && relu)
        tf32gemm_kernel<1, 1, 0, 0><<<grid, 256, GEMM_SMEM_BYTES>>>(
            A, B, bp, C, M, N, K, nullptr, nullptr, nullptr, nullptr);
    else if (bias)
        tf32gemm_kernel<1, 0, 0, 0><<<grid, 256, GEMM_SMEM_BYTES>>>(
            A, B, bp, C, M, N, K, nullptr, nullptr, nullptr, nullptr);
    else
        tf32gemm_kernel<0, 0, 0, 0><<<grid, 256, GEMM_SMEM_BYTES>>>(
            A, B, bp, C, M, N, K, nullptr, nullptr, nullptr, nullptr);
}

extern "C" void kernel_launch(void* const* d_in, const int* in_sizes, int n_in,
                              void* d_out, int out_size) {
    const float* X        = (const float*)d_in[0];
    const int*   ei       = (const int*)d_in[1];
    const float* emb_w    = (const float*)d_in[2];
    const float* emb_b    = (const float*)d_in[3];
    const float* emb_ln_g = (const float*)d_in[4];
    const float* emb_ln_b = (const float*)d_in[5];
    const float* Wq       = (const float*)d_in[6];
    const float* Wk       = (const float*)d_in[7];
    const float* Wv       = (const float*)d_in[8];
    const float* Wo       = (const float*)d_in[9];
    const float* ln_g     = (const float*)d_in[10];
    const float* ln_b     = (const float*)d_in[11];
    const float* f1_w     = (const float*)d_in[12];
    const float* f1_b     = (const float*)d_in[13];
    const float* f2_w     = (const float*)d_in[14];
    const float* f2_b     = (const float*)d_in[15];
    const float* f3_w     = (const float*)d_in[16];
    const float* f3_b     = (const float*)d_in[17];
    float* out = (float*)d_out;

    const int* src = ei;
    const int* dst = ei + EE;

    cudaFuncSetAttribute(tf32gemm_kernel<1, 1, 0, 0>,
                         cudaFuncAttributeMaxDynamicSharedMemorySize, GEMM_SMEM_BYTES);
    cudaFuncSetAttribute(tf32gemm_kernel<1, 0, 0, 0>,
                         cudaFuncAttributeMaxDynamicSharedMemorySize, GEMM_SMEM_BYTES);
    cudaFuncSetAttribute(tf32gemm_kernel<0, 0, 0, 0>,
                         cudaFuncAttributeMaxDynamicSharedMemorySize, GEMM_SMEM_BYTES);
    cudaFuncSetAttribute(tf32gemm_kernel<1, 1, 1, 0>,
                         cudaFuncAttributeMaxDynamicSharedMemorySize, GEMM_SMEM_BYTES);
    cudaFuncSetAttribute(tf32gemm_kernel<0, 0, 1, 0>,
                         cudaFuncAttributeMaxDynamicSharedMemorySize, GEMM_SMEM_BYTES);
    cudaFuncSetAttribute(tf32gemm_kernel<0, 0, 0, 1>,
                         cudaFuncAttributeMaxDynamicSharedMemorySize, GEMM_SMEM_BYTES);

    float *p_h, *p_agg, *p_t, *p_t2, *p_wqkv;
    __half* p_kv;
    cudaGetSymbolAddress((void**)&p_h,    g_h);
    cudaGetSymbolAddress((void**)&p_agg,  g_agg);
    cudaGetSymbolAddress((void**)&p_t,    g_t);
    cudaGetSymbolAddress((void**)&p_t2,   g_t2);
    cudaGetSymbolAddress((void**)&p_wqkv, g_wqkv);
    cudaGetSymbolAddress((void**)&p_kv,   g_kv);

    // ---- CSR build (by dst) + weight packing ----
    zero_deg_kernel<<<(NN + 255) / 256, 256>>>();
    count_deg_kernel<<<(EE + 255) / 256, 256>>>(dst);
    scan_kernel<<<1, 1024>>>();
    scatter_kernel<<<(EE + 255) / 256, 256>>>(src, dst);
    pack_qkv_kernel<<<(LL * DD * DD + 255) / 256, 256>>>(Wq, Wk, Wv);

    // ---- embedding: LN(relu(X @ emb_w + b)) -> h, fused epilogue ----
    {
        dim3 grid(1, (NN + 127) / 128);
        tf32gemm_kernel<1, 1, 1, 0><<<grid, 256, GEMM_SMEM_BYTES>>>(
            X, emb_w, emb_b, p_h, NN, DD, DIN, nullptr, emb_ln_g, emb_ln_b, nullptr);
    }

    // ---- layers ----
    for (int l = 0; l < LL; l++) {
        const float* wo = Wo + (size_t)l * DD * DD;
        // fused qkv: q -> p_t fp32 [N,128]; k,v -> g_kv fp16 [N,256]
        {
            dim3 grid(3, (NN + 127) / 128);
            tf32gemm_kernel<0, 0, 0, 1><<<grid, 256, GEMM_SMEM_BYTES>>>(
                p_h, p_wqkv + (size_t)l * DD * 384, nullptr, p_t, NN, 384, DD,
                nullptr, nullptr, nullptr, p_kv);
        }
        attn_kernel<<<(NN + 7) / 8, 256>>>();
        // h = LN(h + agg @ Wo), fused residual+LN epilogue (in-place on p_h)
        dim3 grid(1, (NN + 127) / 128);
        tf32gemm_kernel<0, 0, 1, 0><<<grid, 256, GEMM_SMEM_BYTES>>>(
            p_agg, wo, nullptr, p_h, NN, DD, DD, p_h, ln_g + l * DD, ln_b + l * DD, nullptr);
    }

    // ---- MLP head ----
    run_gemm(1, 1, p_h,  f1_w, f1_b, p_t,  NN, 512, DD);
    run_gemm(1, 1, p_t,  f2_w, f2_b, p_t2, NN, 512, 512);
    run_gemm(1, 0, p_t2, f3_w, f3_b, out,  NN, NCC, 512);
}

// round 17
// speedup vs baseline: 1.2655x; 1.1504x over previous
#include <cuda_runtime.h>
#include <cuda_fp16.h>
#include <math.h>
#include <math_constants.h>

#define NN 50000
#define EE 640000
#define DIN 256
#define DD 128
#define HH 8
#define NCC 47
#define LL 3

// ---------------- scratch (static device allocations; no runtime alloc) ----
__device__ float  g_h[NN * DD];
__device__ float  g_agg[NN * DD];
__device__ float  g_t[NN * 512];      // q [N,128] per layer
__device__ float  g_t2[NN * 512];     // ff2 out [N,512] fp32
__device__ __half g_th[NN * 512];     // ff1 out [N,512] fp16
__device__ __half g_kv[NN * 256];     // k+v per node, fp16
__device__ __half g_f2wh[512 * 512];  // f2 weights fp16
__device__ float  g_wqkv[LL * DD * 384];
__device__ int    g_deg[NN];
__device__ int    g_off[NN + 1];
__device__ int    g_cur[NN];
__device__ int    g_csr[EE];

// ---------------- CSR build ------------------------------------------------
__global__ void zero_deg_kernel() {
    int i = blockIdx.x * blockDim.x + threadIdx.x;
    if (i < NN) g_deg[i] = 0;
}

__global__ void count_deg_kernel(const int* __restrict__ dst) {
    int e = blockIdx.x * blockDim.x + threadIdx.x;
    if (e < EE) atomicAdd(&g_deg[dst[e]], 1);
}

__global__ void scan_kernel() {
    __shared__ int wsum[32];
    __shared__ int carry_s;
    int t = threadIdx.x, lane = t & 31, wid = t >> 5;
    if (t == 0) carry_s = 0;
    __syncthreads();
    for (int base = 0; base < NN; base += 1024) {
        int i = base + t;
        int val = (i < NN) ? g_deg[i] : 0;
        int incl = val;
        #pragma unroll
        for (int o = 1; o < 32; o <<= 1) {
            int x = __shfl_up_sync(0xFFFFFFFFu, incl, o);
            if (lane >= o) incl += x;
        }
        if (lane == 31) wsum[wid] = incl;
        __syncthreads();
        if (wid == 0) {
            int wv = wsum[lane];
            int wincl = wv;
            #pragma unroll
            for (int o = 1; o < 32; o <<= 1) {
                int x = __shfl_up_sync(0xFFFFFFFFu, wincl, o);
                if (lane >= o) wincl += x;
            }
            wsum[lane] = wincl - wv;
        }
        __syncthreads();
        int carry = carry_s;
        int excl = carry + wsum[wid] + incl - val;
        if (i < NN) { g_off[i] = excl; g_cur[i] = excl; }
        __syncthreads();
        if (t == 1023) carry_s = carry + wsum[31] + incl;
        __syncthreads();
    }
    if (threadIdx.x == 0) g_off[NN] = carry_s;
}

__global__ void scatter_kernel(const int* __restrict__ src, const int* __restrict__ dst) {
    int e = blockIdx.x * blockDim.x + threadIdx.x;
    if (e < EE) {
        int d = dst[e];
        int pos = atomicAdd(&g_cur[d], 1);
        g_csr[pos] = src[e];
    }
}

// ---------------- weight packing -------------------------------------------
__global__ void pack_qkv_kernel(const float* __restrict__ Wq,
                                const float* __restrict__ Wk,
                                const float* __restrict__ Wv) {
    int i = blockIdx.x * blockDim.x + threadIdx.x;
    if (i < LL * DD * DD) {
        int l = i / (DD * DD);
        int r = (i / DD) % DD;
        int c = i % DD;
        size_t o = ((size_t)l * DD + r) * 384;
        g_wqkv[o + c]       = Wq[i];
        g_wqkv[o + 128 + c] = Wk[i];
        g_wqkv[o + 256 + c] = Wv[i];
    }
}

__global__ void pack_f2w_kernel(const float* __restrict__ w) {
    int i = blockIdx.x * blockDim.x + threadIdx.x;
    if (i < 512 * 512) g_f2wh[i] = __float2half(w[i]);
}

__device__ __forceinline__ unsigned f2tf(float f) {
    unsigned u;
    asm("cvt.rna.tf32.f32 %0, %1;" : "=r"(u) : "f"(f));
    return u;
}

#define MMA_TF32(d, a0, a1, a2, a3, b0, b1)                              \
    asm volatile(                                                        \
        "mma.sync.aligned.m16n8k8.row.col.f32.tf32.tf32.f32 "            \
        "{%0,%1,%2,%3}, {%4,%5,%6,%7}, {%8,%9}, {%0,%1,%2,%3};"          \
        : "+f"(d[0]), "+f"(d[1]), "+f"(d[2]), "+f"(d[3])                 \
        : "r"(a0), "r"(a1), "r"(a2), "r"(a3), "r"(b0), "r"(b1))

#define MMA_F16(d, a0, a1, a2, a3, b0, b1)                               \
    asm volatile(                                                        \
        "mma.sync.aligned.m16n8k16.row.col.f32.f16.f16.f32 "             \
        "{%0,%1,%2,%3}, {%4,%5,%6,%7}, {%8,%9}, {%0,%1,%2,%3};"          \
        : "+f"(d[0]), "+f"(d[1]), "+f"(d[2]), "+f"(d[3])                 \
        : "r"(a0), "r"(a1), "r"(a2), "r"(a3), "r"(b0), "r"(b1))

// ============ TF32 GEMM: BM=128,BN=128, 32x64 warp tile, 2 blocks/SM =======
// LN=1: fused LayerNorm epilogue (N==128, grid.x==1), optional residual.
// QKV=1: q fp32 cols [0,128); k/v fp16 -> kvout [N,256]. (N=384)
// OUTH=1: full fp16 output to kvout[rr*N+cc] (N even).
#define GEMM_SMEM_BYTES (2 * 2 * 16 * 136 * 4)

template <int BIAS, int RELU, int LN, int QKV, int OUTH>
__global__ void __launch_bounds__(256, 2)
tf32gemm_kernel(const float* __restrict__ A, const float* __restrict__ B,
                const float* __restrict__ bias, float* __restrict__ C,
                int M, int N, int K,
                const float* __restrict__ resid,
                const float* __restrict__ lngam,
                const float* __restrict__ lnbet,
                __half* __restrict__ kvout) {
    extern __shared__ unsigned sm[];
    unsigned (*As)[16][136] = (unsigned (*)[16][136])sm;
    unsigned (*Bs)[16][136] = (unsigned (*)[16][136])(sm + 2 * 16 * 136);

    int tid = threadIdx.x, lane = tid & 31, wid = tid >> 5;
    int row0 = blockIdx.y * 128, col0 = blockIdx.x * 128;
    int wm = (wid & 3) * 32, wn = (wid >> 2) * 64;
    int g = lane >> 2, c = lane & 3;

    int aRow = tid >> 1, aSeg = tid & 1;
    int bRow = tid >> 5;
    int gr = row0 + aRow;
    int gc = col0 + lane * 4;

    const bool nVec = ((N & 127) == 0);
    const bool nEven = ((N & 1) == 0);

    float acc[2][8][4];
    #pragma unroll
    for (int i = 0; i < 2; i++)
        #pragma unroll
        for (int j = 0; j < 8; j++)
            #pragma unroll
            for (int r = 0; r < 4; r++) acc[i][j][r] = 0.f;

    float4 pa0, pa1, pb0, pb1;

    auto fetch = [&](int k0) {
        pa0 = make_float4(0.f, 0.f, 0.f, 0.f); pa1 = pa0;
        if (gr < M) {
            const float* ap = A + (size_t)gr * K + k0 + aSeg * 8;
            pa0 = ((const float4*)ap)[0];
            pa1 = ((const float4*)ap)[1];
        }
        const float* bp0 = B + (size_t)(k0 + bRow) * N + gc;
        const float* bp1 = B + (size_t)(k0 + bRow + 8) * N + gc;
        if (nVec) {
            pb0 = *(const float4*)bp0;
            pb1 = *(const float4*)bp1;
        } else {
            pb0.x = (gc + 0 < N) ? bp0[0] : 0.f;
            pb0.y = (gc + 1 < N) ? bp0[1] : 0.f;
            pb0.z = (gc + 2 < N) ? bp0[2] : 0.f;
            pb0.w = (gc + 3 < N) ? bp0[3] : 0.f;
            pb1.x = (gc + 0 < N) ? bp1[0] : 0.f;
            pb1.y = (gc + 1 < N) ? bp1[1] : 0.f;
            pb1.z = (gc + 2 < N) ? bp1[2] : 0.f;
            pb1.w = (gc + 3 < N) ? bp1[3] : 0.f;
        }
    };
    auto stage = [&](int s) {
        int kb = aSeg * 8;
        As[s][kb + 0][aRow] = f2tf(pa0.x);
        As[s][kb + 1][aRow] = f2tf(pa0.y);
        As[s][kb + 2][aRow] = f2tf(pa0.z);
        As[s][kb + 3][aRow] = f2tf(pa0.w);
        As[s][kb + 4][aRow] = f2tf(pa1.x);
        As[s][kb + 5][aRow] = f2tf(pa1.y);
        As[s][kb + 6][aRow] = f2tf(pa1.z);
        As[s][kb + 7][aRow] = f2tf(pa1.w);
        uint4 u0 = make_uint4(f2tf(pb0.x), f2tf(pb0.y), f2tf(pb0.z), f2tf(pb0.w));
        uint4 u1 = make_uint4(f2tf(pb1.x), f2tf(pb1.y), f2tf(pb1.z), f2tf(pb1.w));
        *(uint4*)&Bs[s][bRow][lane * 4]     = u0;
        *(uint4*)&Bs[s][bRow + 8][lane * 4] = u1;
    };

    fetch(0);
    stage(0);
    __syncthreads();

    int s = 0;
    for (int k0 = 0; k0 < K; k0 += 16) {
        bool hasNext = (k0 + 16) < K;
        if (hasNext) fetch(k0 + 16);

        #pragma unroll
        for (int ks = 0; ks < 2; ks++) {
            int kb = ks * 8;
            unsigned a[2][4];
            #pragma unroll
            for (int i = 0; i < 2; i++) {
                int m = wm + 16 * i + g;
                a[i][0] = As[s][kb + c][m];
                a[i][1] = As[s][kb + c][m + 8];
                a[i][2] = As[s][kb + c + 4][m];
                a[i][3] = As[s][kb + c + 4][m + 8];
            }
            #pragma unroll
            for (int j = 0; j < 8; j++) {
                unsigned b0 = Bs[s][kb + c][wn + 8 * j + g];
                unsigned b1 = Bs[s][kb + c + 4][wn + 8 * j + g];
                #pragma unroll
                for (int i = 0; i < 2; i++) {
                    MMA_TF32(acc[i][j], a[i][0], a[i][1], a[i][2], a[i][3], b0, b1);
                }
            }
        }

        if (hasNext) {
            stage(s ^ 1);
            __syncthreads();
            s ^= 1;
        }
    }

    if (LN) {
        // ---- fused LayerNorm epilogue (N==128, one block per 128 rows) ----
        __syncthreads();
        float* rsum = (float*)sm;
        float* rsq  = (float*)sm + 256;
        int half_ = wn >> 6;
        #pragma unroll
        for (int i = 0; i < 2; i++) {
            #pragma unroll
            for (int hh = 0; hh < 2; hh++) {
                int lr = wm + 16 * i + 8 * hh + g;
                int rr = row0 + lr;
                float s16 = 0.f, q16 = 0.f;
                #pragma unroll
                for (int j = 0; j < 8; j++) {
                    int cc = wn + 8 * j + 2 * c;
                    float v0 = acc[i][j][2 * hh + 0];
                    float v1 = acc[i][j][2 * hh + 1];
                    if (BIAS) { v0 += bias[cc]; v1 += bias[cc + 1]; }
                    if (RELU) { v0 = fmaxf(v0, 0.f); v1 = fmaxf(v1, 0.f); }
                    if (resid != nullptr && rr < M) {
                        float2 rv = *(const float2*)(resid + (size_t)rr * 128 + cc);
                        v0 += rv.x; v1 += rv.y;
                    }
                    acc[i][j][2 * hh + 0] = v0;
                    acc[i][j][2 * hh + 1] = v1;
                    s16 += v0 + v1;
                    q16 += v0 * v0 + v1 * v1;
                }
                s16 += __shfl_xor_sync(0xFFFFFFFFu, s16, 1);
                s16 += __shfl_xor_sync(0xFFFFFFFFu, s16, 2);
                q16 += __shfl_xor_sync(0xFFFFFFFFu, q16, 1);
                q16 += __shfl_xor_sync(0xFFFFFFFFu, q16, 2);
                if (c == 0) {
                    rsum[half_ * 128 + lr] = s16;
                    rsq [half_ * 128 + lr] = q16;
                }
            }
        }
        __syncthreads();
        #pragma unroll
        for (int i = 0; i < 2; i++) {
            #pragma unroll
            for (int hh = 0; hh < 2; hh++) {
                int lr = wm + 16 * i + 8 * hh + g;
                int rr = row0 + lr;
                if (rr >= M) continue;
                float tot = rsum[lr] + rsum[128 + lr];
                float tq  = rsq[lr]  + rsq[128 + lr];
                float mu  = tot * (1.f / 128.f);
                float var = tq * (1.f / 128.f) - mu * mu;
                float rstd = rsqrtf(var + 1e-5f);
                #pragma unroll
                for (int j = 0; j < 8; j++) {
                    int cc = wn + 8 * j + 2 * c;
                    float2 gg = *(const float2*)(lngam + cc);
                    float2 bb = *(const float2*)(lnbet + cc);
                    float y0 = (acc[i][j][2 * hh + 0] - mu) * rstd * gg.x + bb.x;
                    float y1 = (acc[i][j][2 * hh + 1] - mu) * rstd * gg.y + bb.y;
                    *(float2*)(C + (size_t)rr * 128 + cc) = make_float2(y0, y1);
                }
            }
        }
        return;
    }

    if (QKV) {
        // ---- qkv epilogue: q fp32 [N,128], k/v fp16 packed [N,256] ----
        #pragma unroll
        for (int i = 0; i < 2; i++) {
            int r = row0 + wm + 16 * i + g;
            #pragma unroll
            for (int j = 0; j < 8; j++) {
                int cc = col0 + wn + 8 * j + 2 * c;
                #pragma unroll
                for (int hh = 0; hh < 2; hh++) {
                    int rr = r + hh * 8;
                    if (rr < M) {
                        float v0 = acc[i][j][hh * 2 + 0];
                        float v1 = acc[i][j][hh * 2 + 1];
                        if (cc < 128) {
                            *(float2*)(C + (size_t)rr * 128 + cc) = make_float2(v0, v1);
                        } else {
                            __half2 hv = __floats2half2_rn(v0, v1);
                            *(__half2*)(kvout + (size_t)rr * 256 + (cc - 128)) = hv;
                        }
                    }
                }
            }
        }
        return;
    }

    if (OUTH) {
        // ---- fp16 output epilogue (N even) ----
        #pragma unroll
        for (int i = 0; i < 2; i++) {
            int r = row0 + wm + 16 * i + g;
            #pragma unroll
            for (int j = 0; j < 8; j++) {
                int cc = col0 + wn + 8 * j + 2 * c;
                #pragma unroll
                for (int hh = 0; hh < 2; hh++) {
                    int rr = r + hh * 8;
                    if (rr < M) {
                        float v0 = acc[i][j][hh * 2 + 0];
                        float v1 = acc[i][j][hh * 2 + 1];
                        if (BIAS) { v0 += bias[cc]; v1 += bias[cc + 1]; }
                        if (RELU) { v0 = fmaxf(v0, 0.f); v1 = fmaxf(v1, 0.f); }
                        __half2 hv = __floats2half2_rn(v0, v1);
                        *(__half2*)(kvout + (size_t)rr * N + cc) = hv;
                    }
                }
            }
        }
        return;
    }

    // ---- plain epilogue ----
    #pragma unroll
    for (int i = 0; i < 2; i++) {
        int r = row0 + wm + 16 * i + g;
        #pragma unroll
        for (int j = 0; j < 8; j++) {
            int cc = col0 + wn + 8 * j + 2 * c;
            #pragma unroll
            for (int hh = 0; hh < 2; hh++) {
                int rr = r + hh * 8;
                if (rr < M) {
                    float v0 = acc[i][j][hh * 2 + 0];
                    float v1 = acc[i][j][hh * 2 + 1];
                    float* cp = C + (size_t)rr * N + cc;
                    if (nEven) {
                        if (cc + 1 < N) {
                            if (BIAS) { v0 += bias[cc]; v1 += bias[cc + 1]; }
                            if (RELU) { v0 = fmaxf(v0, 0.f); v1 = fmaxf(v1, 0.f); }
                            *(float2*)cp = make_float2(v0, v1);
                        } else if (cc < N) {
                            if (BIAS) v0 += bias[cc];
                            if (RELU) v0 = fmaxf(v0, 0.f);
                            cp[0] = v0;
                        }
                    } else {
                        if (cc < N) {
                            if (BIAS) v0 += bias[cc];
                            if (RELU) v0 = fmaxf(v0, 0.f);
                            cp[0] = v0;
                        }
                        if (cc + 1 < N) {
                            if (BIAS) v1 += bias[cc + 1];
                            if (RELU) v1 = fmaxf(v1, 0.f);
                            cp[1] = v1;
                        }
                    }
                }
            }
        }
    }
}

// ============ FP16 GEMM: BM=128,BN=128,BK=32, m16n8k16, 2 blocks/SM ========
// A fp16 [M,K] (K%32==0), B fp16 [K,N] (N%128==0), C fp32 + bias/relu.
// As: [2][128 rows][20 u32] (32 halves + pad); Bs: [2][16 k-pairs][136 u32]
// (half2 = k-pair per word). All fragment loads verified conflict-free.
#define HA_U32 (128 * 20)
#define HB_U32 (16 * 136)
#define HGEMM_SMEM_BYTES (2 * (HA_U32 + HB_U32) * 4)

template <int BIAS, int RELU>
__global__ void __launch_bounds__(256, 2)
h16gemm_kernel(const __half* __restrict__ A, const __half* __restrict__ B,
               const float* __restrict__ bias, float* __restrict__ C,
               int M, int N, int K) {
    extern __shared__ unsigned sm[];
    unsigned* AsB = sm;                 // [2][128][20]
    unsigned* BsB = sm + 2 * HA_U32;    // [2][16][136]

    int tid = threadIdx.x, lane = tid & 31, wid = tid >> 5;
    int row0 = blockIdx.y * 128, col0 = blockIdx.x * 128;
    int wm = (wid & 3) * 32, wn = (wid >> 2) * 64;
    int g = lane >> 2, c = lane & 3;

    int aRow = tid >> 1, aSeg = tid & 1;   // A: row aRow, halves [aSeg*16, +16)
    int gr = row0 + aRow;
    int bk2 = tid >> 4;                    // k-pair 0..15
    int bn0 = (tid & 15) * 8;              // 8 n's per thread
    int gc = col0 + bn0;

    float acc[2][8][4];
    #pragma unroll
    for (int i = 0; i < 2; i++)
        #pragma unroll
        for (int j = 0; j < 8; j++)
            #pragma unroll
            for (int r = 0; r < 4; r++) acc[i][j][r] = 0.f;

    uint4 pa0, pa1, pb0, pb1;

    auto fetch = [&](int k0) {
        pa0 = make_uint4(0, 0, 0, 0); pa1 = pa0;
        if (gr < M) {
            const __half* ap = A + (size_t)gr * K + k0 + aSeg * 16;
            pa0 = ((const uint4*)ap)[0];
            pa1 = ((const uint4*)ap)[1];
        }
        pb0 = *(const uint4*)(B + (size_t)(k0 + 2 * bk2) * N + gc);
        pb1 = *(const uint4*)(B + (size_t)(k0 + 2 * bk2 + 1) * N + gc);
    };
    auto stage = [&](int s) {
        unsigned* ap = AsB + s * HA_U32 + aRow * 20 + aSeg * 8;
        *(uint4*)ap       = pa0;
        *(uint4*)(ap + 4) = pa1;
        unsigned ea[4] = {pb0.x, pb0.y, pb0.z, pb0.w};
        unsigned eb[4] = {pb1.x, pb1.y, pb1.z, pb1.w};
        unsigned o[8];
        #pragma unroll
        for (int w = 0; w < 4; w++) {
            o[2 * w + 0] = __byte_perm(ea[w], eb[w], 0x5410);  // {k lo, k+1 lo}
            o[2 * w + 1] = __byte_perm(ea[w], eb[w], 0x7632);  // {k hi, k+1 hi}
        }
        unsigned* bp = BsB + s * HB_U32 + bk2 * 136 + bn0;
        *(uint4*)bp       = make_uint4(o[0], o[1], o[2], o[3]);
        *(uint4*)(bp + 4) = make_uint4(o[4], o[5], o[6], o[7]);
    };

    fetch(0);
    stage(0);
    __syncthreads();

    int s = 0;
    for (int k0 = 0; k0 < K; k0 += 32) {
        bool hasNext = (k0 + 32) < K;
        if (hasNext) fetch(k0 + 32);

        const unsigned* as = AsB + s * HA_U32;
        const unsigned* bs = BsB + s * HB_U32;
        #pragma unroll
        for (int ks = 0; ks < 2; ks++) {
            unsigned a[2][4];
            #pragma unroll
            for (int i = 0; i < 2; i++) {
                int m = wm + 16 * i + g;
                const unsigned* r0 = as + m * 20 + ks * 8;
                const unsigned* r1 = as + (m + 8) * 20 + ks * 8;
                a[i][0] = r0[c];
                a[i][1] = r1[c];
                a[i][2] = r0[c + 4];
                a[i][3] = r1[c + 4];
            }
            #pragma unroll
            for (int j = 0; j < 8; j++) {
                int n = wn + 8 * j + g;
                unsigned b0 = bs[(ks * 8 + c) * 136 + n];
                unsigned b1 = bs[(ks * 8 + c + 4) * 136 + n];
                #pragma unroll
                for (int i = 0; i < 2; i++) {
                    MMA_F16(acc[i][j], a[i][0], a[i][1], a[i][2], a[i][3], b0, b1);
                }
            }
        }

        if (hasNext) {
            stage(s ^ 1);
            __syncthreads();
            s ^= 1;
        }
    }

    // epilogue: fp32 out, N even -> float2 stores
    #pragma unroll
    for (int i = 0; i < 2; i++) {
        int r = row0 + wm + 16 * i + g;
        #pragma unroll
        for (int j = 0; j < 8; j++) {
            int cc = col0 + wn + 8 * j + 2 * c;
            #pragma unroll
            for (int hh = 0; hh < 2; hh++) {
                int rr = r + hh * 8;
                if (rr < M) {
                    float v0 = acc[i][j][hh * 2 + 0];
                    float v1 = acc[i][j][hh * 2 + 1];
                    if (BIAS) { v0 += bias[cc]; v1 += bias[cc + 1]; }
                    if (RELU) { v0 = fmaxf(v0, 0.f); v1 = fmaxf(v1, 0.f); }
                    *(float2*)(C + (size_t)rr * N + cc) = make_float2(v0, v1);
                }
            }
        }
    }
}

// ---------------- attention + aggregation (warp per dst node) --------------
__device__ __forceinline__ float dot4h(const float4& q, uint2 ku) {
    float2 a = __half22float2(*(__half2*)&ku.x);
    float2 b = __half22float2(*(__half2*)&ku.y);
    return q.x * a.x + q.y * a.y + q.z * b.x + q.w * b.y;
}

__global__ void attn_kernel() {
    int node = blockIdx.x * (blockDim.x >> 5) + (threadIdx.x >> 5);
    if (node >= NN) return;
    int lane = threadIdx.x & 31;
    float4 qv = ((const float4*)(g_t + (size_t)node * 128))[lane];
    float s = 0.f;
    float4 acc = make_float4(0.f, 0.f, 0.f, 0.f);
    int e0 = g_off[node], e1 = g_off[node + 1];
    int e = e0;
    for (; e + 4 <= e1; e += 4) {
        const __half* b0 = g_kv + (size_t)g_csr[e + 0] * 256;
        const __half* b1 = g_kv + (size_t)g_csr[e + 1] * 256;
        const __half* b2 = g_kv + (size_t)g_csr[e + 2] * 256;
        const __half* b3 = g_kv + (size_t)g_csr[e + 3] * 256;
        uint2 k0 = ((const uint2*)b0)[lane];
        uint2 k1 = ((const uint2*)b1)[lane];
        uint2 k2 = ((const uint2*)b2)[lane];
        uint2 k3 = ((const uint2*)b3)[lane];
        uint2 v0 = ((const uint2*)(b0 + 128))[lane];
        uint2 v1 = ((const uint2*)(b1 + 128))[lane];
        uint2 v2 = ((const uint2*)(b2 + 128))[lane];
        uint2 v3 = ((const uint2*)(b3 + 128))[lane];
        float d0 = dot4h(qv, k0);
        float d1 = dot4h(qv, k1);
        float d2 = dot4h(qv, k2);
        float d3 = dot4h(qv, k3);
        d0 += __shfl_xor_sync(0xFFFFFFFFu, d0, 1);
        d0 += __shfl_xor_sync(0xFFFFFFFFu, d0, 2);
        d1 += __shfl_xor_sync(0xFFFFFFFFu, d1, 1);
        d1 += __shfl_xor_sync(0xFFFFFFFFu, d1, 2);
        d2 += __shfl_xor_sync(0xFFFFFFFFu, d2, 1);
        d2 += __shfl_xor_sync(0xFFFFFFFFu, d2, 2);
        d3 += __shfl_xor_sync(0xFFFFFFFFu, d3, 1);
        d3 += __shfl_xor_sync(0xFFFFFFFFu, d3, 2);
        float w0 = __expf(d0 * 0.25f);
        float w1 = __expf(d1 * 0.25f);
        float w2 = __expf(d2 * 0.25f);
        float w3 = __expf(d3 * 0.25f);
        s += (w0 + w1) + (w2 + w3);
        float2 a0 = __half22float2(*(__half2*)&v0.x), c0 = __half22float2(*(__half2*)&v0.y);
        float2 a1 = __half22float2(*(__half2*)&v1.x), c1 = __half22float2(*(__half2*)&v1.y);
        float2 a2 = __half22float2(*(__half2*)&v2.x), c2 = __half22float2(*(__half2*)&v2.y);
        float2 a3 = __half22float2(*(__half2*)&v3.x), c3 = __half22float2(*(__half2*)&v3.y);
        acc.x += w0 * a0.x + w1 * a1.x + w2 * a2.x + w3 * a3.x;
        acc.y += w0 * a0.y + w1 * a1.y + w2 * a2.y + w3 * a3.y;
        acc.z += w0 * c0.x + w1 * c1.x + w2 * c2.x + w3 * c3.x;
        acc.w += w0 * c0.y + w1 * c1.y + w2 * c2.y + w3 * c3.y;
    }
    for (; e < e1; e++) {
        const __half* b0 = g_kv + (size_t)g_csr[e] * 256;
        uint2 k0 = ((const uint2*)b0)[lane];
        uint2 v0 = ((const uint2*)(b0 + 128))[lane];
        float d0 = dot4h(qv, k0);
        d0 += __shfl_xor_sync(0xFFFFFFFFu, d0, 1);
        d0 += __shfl_xor_sync(0xFFFFFFFFu, d0, 2);
        float w0 = __expf(d0 * 0.25f);
        s += w0;
        float2 a0 = __half22float2(*(__half2*)&v0.x), c0 = __half22float2(*(__half2*)&v0.y);
        acc.x += w0 * a0.x; acc.y += w0 * a0.y;
        acc.z += w0 * c0.x; acc.w += w0 * c0.y;
    }
    float inv = (s > 0.f) ? 1.f / s : 0.f;
    float4 o = make_float4(acc.x * inv, acc.y * inv, acc.z * inv, acc.w * inv);
    ((float4*)(g_agg + (size_t)node * DD))[lane] = o;
}

// ---------------- host-side launch -----------------------------------------
static inline void run_gemm(int bias, int relu, const float* A, const float* B,
                            const float* bp, float* C, int M, int N, int K) {
    dim3 grid((N + 127) / 128, (M + 127) / 128);
    if (bias && relu)
        tf32gemm_kernel<1, 1, 0, 0, 0><<<grid, 256, GEMM_SMEM_BYTES>>>(
            A, B, bp, C, M, N, K, nullptr, nullptr, nullptr, nullptr);
    else if (bias)
        tf32gemm_kernel<1, 0, 0, 0, 0><<<grid, 256, GEMM_SMEM_BYTES>>>(
            A, B, bp, C, M, N, K, nullptr, nullptr, nullptr, nullptr);
    else
        tf32gemm_kernel<0, 0, 0, 0, 0><<<grid, 256, GEMM_SMEM_BYTES>>>(
            A, B, bp, C, M, N, K, nullptr, nullptr, nullptr, nullptr);
}

extern "C" void kernel_launch(void* const* d_in, const int* in_sizes, int n_in,
                              void* d_out, int out_size) {
    const float* X        = (const float*)d_in[0];
    const int*   ei       = (const int*)d_in[1];
    const float* emb_w    = (const float*)d_in[2];
    const float* emb_b    = (const float*)d_in[3];
    const float* emb_ln_g = (const float*)d_in[4];
    const float* emb_ln_b = (const float*)d_in[5];
    const float* Wq       = (const float*)d_in[6];
    const float* Wk       = (const float*)d_in[7];
    const float* Wv       = (const float*)d_in[8];
    const float* Wo       = (const float*)d_in[9];
    const float* ln_g     = (const float*)d_in[10];
    const float* ln_b     = (const float*)d_in[11];
    const float* f1_w     = (const float*)d_in[12];
    const float* f1_b     = (const float*)d_in[13];
    const float* f2_w     = (const float*)d_in[14];
    const float* f2_b     = (const float*)d_in[15];
    const float* f3_w     = (const float*)d_in[16];
    const float* f3_b     = (const float*)d_in[17];
    float* out = (float*)d_out;

    const int* src = ei;
    const int* dst = ei + EE;

    cudaFuncSetAttribute(tf32gemm_kernel<1, 1, 0, 0, 0>,
                         cudaFuncAttributeMaxDynamicSharedMemorySize, GEMM_SMEM_BYTES);
    cudaFuncSetAttribute(tf32gemm_kernel<1, 0, 0, 0, 0>,
                         cudaFuncAttributeMaxDynamicSharedMemorySize, GEMM_SMEM_BYTES);
    cudaFuncSetAttribute(tf32gemm_kernel<0, 0, 0, 0, 0>,
                         cudaFuncAttributeMaxDynamicSharedMemorySize, GEMM_SMEM_BYTES);
    cudaFuncSetAttribute(tf32gemm_kernel<1, 1, 1, 0, 0>,
                         cudaFuncAttributeMaxDynamicSharedMemorySize, GEMM_SMEM_BYTES);
    cudaFuncSetAttribute(tf32gemm_kernel<0, 0, 1, 0, 0>,
                         cudaFuncAttributeMaxDynamicSharedMemorySize, GEMM_SMEM_BYTES);
    cudaFuncSetAttribute(tf32gemm_kernel<0, 0, 0, 1, 0>,
                         cudaFuncAttributeMaxDynamicSharedMemorySize, GEMM_SMEM_BYTES);
    cudaFuncSetAttribute(tf32gemm_kernel<1, 1, 0, 0, 1>,
                         cudaFuncAttributeMaxDynamicSharedMemorySize, GEMM_SMEM_BYTES);
    cudaFuncSetAttribute(h16gemm_kernel<1, 1>,
                         cudaFuncAttributeMaxDynamicSharedMemorySize, HGEMM_SMEM_BYTES);

    float *p_h, *p_agg, *p_t, *p_t2, *p_wqkv;
    __half *p_kv, *p_th, *p_f2wh;
    cudaGetSymbolAddress((void**)&p_h,    g_h);
    cudaGetSymbolAddress((void**)&p_agg,  g_agg);
    cudaGetSymbolAddress((void**)&p_t,    g_t);
    cudaGetSymbolAddress((void**)&p_t2,   g_t2);
    cudaGetSymbolAddress((void**)&p_wqkv, g_wqkv);
    cudaGetSymbolAddress((void**)&p_kv,   g_kv);
    cudaGetSymbolAddress((void**)&p_th,   g_th);
    cudaGetSymbolAddress((void**)&p_f2wh, g_f2wh);

    // ---- CSR build (by dst) + weight packing ----
    zero_deg_kernel<<<(NN + 255) / 256, 256>>>();
    count_deg_kernel<<<(EE + 255) / 256, 256>>>(dst);
    scan_kernel<<<1, 1024>>>();
    scatter_kernel<<<(EE + 255) / 256, 256>>>(src, dst);
    pack_qkv_kernel<<<(LL * DD * DD + 255) / 256, 256>>>(Wq, Wk, Wv);
    pack_f2w_kernel<<<(512 * 512 + 255) / 256, 256>>>(f2_w);

    // ---- embedding: LN(relu(X @ emb_w + b)) -> h, fused epilogue ----
    {
        dim3 grid(1, (NN + 127) / 128);
        tf32gemm_kernel<1, 1, 1, 0, 0><<<grid, 256, GEMM_SMEM_BYTES>>>(
            X, emb_w, emb_b, p_h, NN, DD, DIN, nullptr, emb_ln_g, emb_ln_b, nullptr);
    }

    // ---- layers ----
    for (int l = 0; l < LL; l++) {
        const float* wo = Wo + (size_t)l * DD * DD;
        // fused qkv: q -> p_t fp32 [N,128]; k,v -> g_kv fp16 [N,256]
        {
            dim3 grid(3, (NN + 127) / 128);
            tf32gemm_kernel<0, 0, 0, 1, 0><<<grid, 256, GEMM_SMEM_BYTES>>>(
                p_h, p_wqkv + (size_t)l * DD * 384, nullptr, p_t, NN, 384, DD,
                nullptr, nullptr, nullptr, p_kv);
        }
        attn_kernel<<<(NN + 7) / 8, 256>>>();
        // h = LN(h + agg @ Wo), fused residual+LN epilogue (in-place on p_h)
        dim3 grid(1, (NN + 127) / 128);
        tf32gemm_kernel<0, 0, 1, 0, 0><<<grid, 256, GEMM_SMEM_BYTES>>>(
            p_agg, wo, nullptr, p_h, NN, DD, DD, p_h, ln_g + l * DD, ln_b + l * DD, nullptr);
    }

    // ---- MLP head ----
    // f1: tf32 GEMM, fp16 output -> g_th
    {
        dim3 grid(4, (NN + 127) / 128);
        tf32gemm_kernel<1, 1, 0, 0, 1><<<grid, 256, GEMM_SMEM_BYTES>>>(
            p_h, f1_w, f1_b, nullptr, NN, 512, DD, nullptr, nullptr, nullptr, p_th);
    }
    // f2: fp16 tensor-core GEMM -> g_t2 fp32
    {
        dim3 grid(4, (NN + 127) / 128);
        h16gemm_kernel<1, 1><<<grid, 256, HGEMM_SMEM_BYTES>>>(
            p_th, p_f2wh, f2_b, p_t2, NN, 512, 512);
    }
    // f3: tf32 (odd N path)
    run_gemm(1, 0, p_t2, f3_w, f3_b, out, NN, NCC, 512);
}